// round 4
// baseline (speedup 1.0000x reference)
#include <cuda_runtime.h>
#include <math.h>
#include <stdint.h>

#define N_NODES 50000
#define HIDDEN  128
#define FFN     256
#define LN_EPS  1e-5f

// ---------------- scratch (static device globals; no allocation) ----------
__device__ float g_aln[(size_t)N_NODES * HIDDEN];   // LN1(x)
__device__ float g_h  [(size_t)N_NODES * FFN];      // gelu(ln1 @ w_in^T + b_in)
__device__ float g_gln[(size_t)N_NODES * FFN];      // LN2(h); later reused as hg
__device__ float g_xw [(size_t)N_NODES * FFN];      // gln @ w_gcn^T
__device__ float g_agg[(size_t)N_NODES * FFN];      // gcn aggregation
__device__ float g_dinv[N_NODES];                   // deg -> rsqrt(deg)
__device__ int   g_is64;

// ---------------- dtype detect: int64 edge_index has zero high words -------
__global__ void k_detect(const unsigned int* __restrict__ w, int nslots) {
    __shared__ unsigned int red[256];
    unsigned int acc = 0;
    for (int i = threadIdx.x; i < nslots; i += blockDim.x) acc |= w[2 * i + 1];
    red[threadIdx.x] = acc;
    __syncthreads();
    for (int s = 128; s > 0; s >>= 1) {
        if (threadIdx.x < s) red[threadIdx.x] |= red[threadIdx.x + s];
        __syncthreads();
    }
    if (threadIdx.x == 0) g_is64 = (red[0] == 0u) ? 1 : 0;
}

// ---------------- degree / dinv -------------------------------------------
__global__ void k_deg_init() {
    int i = blockIdx.x * blockDim.x + threadIdx.x;
    if (i < N_NODES) g_dinv[i] = 2.0f;   // self-loop weight 2
}
__global__ void k_deg_acc(const void* __restrict__ eidx, int E) {
    int e = blockIdx.x * blockDim.x + threadIdx.x;
    if (e >= E) return;
    int d;
    if (g_is64) d = (int)((const long long*)eidx)[E + e];
    else        d = ((const int*)eidx)[E + e];
    atomicAdd(&g_dinv[d], 1.0f);
}
__global__ void k_dinv_fin() {
    int i = blockIdx.x * blockDim.x + threadIdx.x;
    if (i < N_NODES) g_dinv[i] = rsqrtf(g_dinv[i]);
}

// ---------------- LayerNorm (warp per node) --------------------------------
__global__ void k_ln128(const float* __restrict__ x, const float* __restrict__ g,
                        const float* __restrict__ b, float* __restrict__ out) {
    int warp = (blockIdx.x * blockDim.x + threadIdx.x) >> 5;
    if (warp >= N_NODES) return;
    int lane = threadIdx.x & 31;
    float4 v = ((const float4*)(x + (size_t)warp * 128))[lane];
    float s  = v.x + v.y + v.z + v.w;
    float sq = v.x * v.x + v.y * v.y + v.z * v.z + v.w * v.w;
    #pragma unroll
    for (int o = 16; o; o >>= 1) {
        s  += __shfl_xor_sync(0xffffffffu, s,  o);
        sq += __shfl_xor_sync(0xffffffffu, sq, o);
    }
    float mu  = s * (1.0f / 128.0f);
    float var = sq * (1.0f / 128.0f) - mu * mu;
    float r   = rsqrtf(var + LN_EPS);
    float4 gg = ((const float4*)g)[lane];
    float4 bb = ((const float4*)b)[lane];
    float4 o4;
    o4.x = (v.x - mu) * r * gg.x + bb.x;
    o4.y = (v.y - mu) * r * gg.y + bb.y;
    o4.z = (v.z - mu) * r * gg.z + bb.z;
    o4.w = (v.w - mu) * r * gg.w + bb.w;
    ((float4*)(out + (size_t)warp * 128))[lane] = o4;
}

__global__ void k_ln256(const float* __restrict__ x, const float* __restrict__ g,
                        const float* __restrict__ b, float* __restrict__ out) {
    int warp = (blockIdx.x * blockDim.x + threadIdx.x) >> 5;
    if (warp >= N_NODES) return;
    int lane = threadIdx.x & 31;
    const float4* xr = (const float4*)(x + (size_t)warp * 256);
    float4 v0 = xr[lane], v1 = xr[lane + 32];
    float s  = v0.x + v0.y + v0.z + v0.w + v1.x + v1.y + v1.z + v1.w;
    float sq = v0.x*v0.x + v0.y*v0.y + v0.z*v0.z + v0.w*v0.w
             + v1.x*v1.x + v1.y*v1.y + v1.z*v1.z + v1.w*v1.w;
    #pragma unroll
    for (int o = 16; o; o >>= 1) {
        s  += __shfl_xor_sync(0xffffffffu, s,  o);
        sq += __shfl_xor_sync(0xffffffffu, sq, o);
    }
    float mu  = s * (1.0f / 256.0f);
    float var = sq * (1.0f / 256.0f) - mu * mu;
    float r   = rsqrtf(var + LN_EPS);
    const float4* g4 = (const float4*)g;
    const float4* b4 = (const float4*)b;
    float4* outr = (float4*)(out + (size_t)warp * 256);
    #pragma unroll
    for (int i = 0; i < 2; i++) {
        float4 v  = (i == 0) ? v0 : v1;
        float4 gg = g4[lane + i * 32];
        float4 bb = b4[lane + i * 32];
        float4 o4;
        o4.x = (v.x - mu) * r * gg.x + bb.x;
        o4.y = (v.y - mu) * r * gg.y + bb.y;
        o4.z = (v.z - mu) * r * gg.z + bb.z;
        o4.w = (v.w - mu) * r * gg.w + bb.w;
        outr[lane + i * 32] = o4;
    }
}

// ---------------- tf32 helpers ---------------------------------------------
__device__ __forceinline__ float f2tf32(float x) {
    unsigned r;
    asm("cvt.rna.tf32.f32 %0, %1;" : "=r"(r) : "f"(x));
    return __uint_as_float(r);
}
__device__ __forceinline__ void mma_tf32(float* c, const float* a, const float* b) {
    asm volatile(
        "mma.sync.aligned.m16n8k8.row.col.f32.tf32.tf32.f32 "
        "{%0,%1,%2,%3}, {%4,%5,%6,%7}, {%8,%9}, {%0,%1,%2,%3};"
        : "+f"(c[0]), "+f"(c[1]), "+f"(c[2]), "+f"(c[3])
        : "r"(__float_as_uint(a[0])), "r"(__float_as_uint(a[1])),
          "r"(__float_as_uint(a[2])), "r"(__float_as_uint(a[3])),
          "r"(__float_as_uint(b[0])), "r"(__float_as_uint(b[1])));
}

// EPI: 0 = bias only, 1 = gelu(x + bias)
template <int EPI>
__device__ __forceinline__ float epi_apply(float v) {
    if (EPI == 1) return 0.5f * v * (1.0f + erff(v * 0.70710678118654752f));
    return v;
}

// C[M,N] = A[M,K] @ W[N,K]^T (+bias) (+epilogue). BM=128, BN=64, BK=32, 256 thr.
template <int K, int EPI>
__global__ __launch_bounds__(256) void k_gemm(
    const float* __restrict__ A, const float* __restrict__ W,
    const float* __restrict__ bias, float* __restrict__ C, int M, int N) {
    const int BM = 128, BN = 64, BK = 32;
    __shared__ float As[BM][BK + 4];   // pad 4 -> conflict-free frag loads
    __shared__ float Bs[BK][BN + 8];   // pad 8 -> conflict-free frag loads
    int tid = threadIdx.x;
    int wid = tid >> 5, lane = tid & 31;
    int wm = wid >> 1, wn = wid & 1;        // 4 x 2 warp grid, warp tile 32x32
    int g = lane >> 2, tq = lane & 3;
    int bm0 = blockIdx.x * BM, bn0 = blockIdx.y * BN;

    float acc[2][4][4];
    #pragma unroll
    for (int mt = 0; mt < 2; mt++)
        #pragma unroll
        for (int nt = 0; nt < 4; nt++)
            #pragma unroll
            for (int i = 0; i < 4; i++) acc[mt][nt][i] = 0.0f;

    for (int k0 = 0; k0 < K; k0 += BK) {
        // A tile: 128x32 = 1024 float4
        #pragma unroll
        for (int i = 0; i < 4; i++) {
            int idx = tid + i * 256;
            int row = idx >> 3, c4 = idx & 7;
            float4 v = make_float4(0.f, 0.f, 0.f, 0.f);
            int gr = bm0 + row;
            if (gr < M) v = *(const float4*)(A + (size_t)gr * K + k0 + c4 * 4);
            float* d = &As[row][c4 * 4];
            d[0] = f2tf32(v.x); d[1] = f2tf32(v.y);
            d[2] = f2tf32(v.z); d[3] = f2tf32(v.w);
        }
        // B tile (transpose W[n][k] -> Bs[k][n]): 512 float4 reads
        #pragma unroll
        for (int i = 0; i < 2; i++) {
            int idx = tid + i * 256;
            int n = idx >> 3, c4 = idx & 7;
            float4 v = *(const float4*)(W + (size_t)(bn0 + n) * K + k0 + c4 * 4);
            Bs[c4 * 4 + 0][n] = f2tf32(v.x);
            Bs[c4 * 4 + 1][n] = f2tf32(v.y);
            Bs[c4 * 4 + 2][n] = f2tf32(v.z);
            Bs[c4 * 4 + 3][n] = f2tf32(v.w);
        }
        __syncthreads();
        #pragma unroll
        for (int ks = 0; ks < BK / 8; ks++) {
            float af[2][4], bf[4][2];
            #pragma unroll
            for (int mt = 0; mt < 2; mt++) {
                int rb = wm * 32 + mt * 16;
                af[mt][0] = As[rb + g    ][ks * 8 + tq];
                af[mt][1] = As[rb + g + 8][ks * 8 + tq];
                af[mt][2] = As[rb + g    ][ks * 8 + tq + 4];
                af[mt][3] = As[rb + g + 8][ks * 8 + tq + 4];
            }
            #pragma unroll
            for (int nt = 0; nt < 4; nt++) {
                int cb = wn * 32 + nt * 8;
                bf[nt][0] = Bs[ks * 8 + tq    ][cb + g];
                bf[nt][1] = Bs[ks * 8 + tq + 4][cb + g];
            }
            #pragma unroll
            for (int mt = 0; mt < 2; mt++)
                #pragma unroll
                for (int nt = 0; nt < 4; nt++)
                    mma_tf32(acc[mt][nt], af[mt], bf[nt]);
        }
        __syncthreads();
    }

    // epilogue
    #pragma unroll
    for (int mt = 0; mt < 2; mt++) {
        int r0 = bm0 + wm * 32 + mt * 16 + g;
        #pragma unroll
        for (int nt = 0; nt < 4; nt++) {
            int c0 = bn0 + wn * 32 + nt * 8 + 2 * tq;
            float bv0 = bias ? bias[c0]     : 0.0f;
            float bv1 = bias ? bias[c0 + 1] : 0.0f;
            if (r0 < M) {
                C[(size_t)r0 * N + c0]     = epi_apply<EPI>(acc[mt][nt][0] + bv0);
                C[(size_t)r0 * N + c0 + 1] = epi_apply<EPI>(acc[mt][nt][1] + bv1);
            }
            if (r0 + 8 < M) {
                C[(size_t)(r0 + 8) * N + c0]     = epi_apply<EPI>(acc[mt][nt][2] + bv0);
                C[(size_t)(r0 + 8) * N + c0 + 1] = epi_apply<EPI>(acc[mt][nt][3] + bv1);
            }
        }
    }
}

// ---------------- GCN aggregation ------------------------------------------
// agg[i][:] = b_gcn[:] + xw[i][:] * (2*dinv[i]^2)   (self-loop, ew=2)
__global__ void k_agg_init(const float* __restrict__ bg) {
    int i = blockIdx.x * blockDim.x + threadIdx.x;
    if (i >= N_NODES * (FFN / 4)) return;
    int node = i / (FFN / 4);
    int c4   = i % (FFN / 4);
    float dv = g_dinv[node];
    float coef = 2.0f * dv * dv;
    float4 v = ((const float4*)g_xw)[i];
    float4 b = ((const float4*)bg)[c4];
    float4 o;
    o.x = b.x + v.x * coef; o.y = b.y + v.y * coef;
    o.z = b.z + v.z * coef; o.w = b.w + v.w * coef;
    ((float4*)g_agg)[i] = o;
}

// one warp per edge: agg[dst] += xw[src] * dinv[src]*dinv[dst]
__global__ void k_scatter(const void* __restrict__ eidx, int E) {
    int gt = blockIdx.x * blockDim.x + threadIdx.x;
    int e = gt >> 5;
    if (e >= E) return;
    int lane = gt & 31;
    int s, d;
    if (g_is64) {
        const long long* p = (const long long*)eidx;
        s = (int)p[e]; d = (int)p[E + e];
    } else {
        const int* p = (const int*)eidx;
        s = p[e]; d = p[E + e];
    }
    float coef = g_dinv[s] * g_dinv[d];
    const float4* src = (const float4*)(g_xw + (size_t)s * FFN);
    float4*       dst = (float4*)(g_agg + (size_t)d * FFN);
    #pragma unroll
    for (int i = 0; i < 2; i++) {
        float4 v = src[lane + i * 32];
        v.x *= coef; v.y *= coef; v.z *= coef; v.w *= coef;
        asm volatile("red.global.add.v4.f32 [%0], {%1,%2,%3,%4};"
                     :: "l"(dst + lane + i * 32),
                        "f"(v.x), "f"(v.y), "f"(v.z), "f"(v.w)
                     : "memory");
    }
}

// hg = tanh(agg) * h  -> stored into g_gln (reused)
__global__ void k_combine() {
    int i = blockIdx.x * blockDim.x + threadIdx.x;
    if (i >= N_NODES * (FFN / 4)) return;
    float4 a = ((const float4*)g_agg)[i];
    float4 h = ((const float4*)g_h)[i];
    float4 o;
    o.x = tanhf(a.x) * h.x; o.y = tanhf(a.y) * h.y;
    o.z = tanhf(a.z) * h.z; o.w = tanhf(a.w) * h.w;
    ((float4*)g_gln)[i] = o;
}

// ---------------- host ------------------------------------------------------
extern "C" void kernel_launch(void* const* d_in, const int* in_sizes, int n_in,
                              void* d_out, int out_size) {
    const float* x     = (const float*)d_in[0];
    const void*  eidx  = d_in[1];
    const float* ln1_g = (const float*)d_in[2];
    const float* ln1_b = (const float*)d_in[3];
    const float* w_in  = (const float*)d_in[4];
    const float* b_in  = (const float*)d_in[5];
    const float* ln2_g = (const float*)d_in[6];
    const float* ln2_b = (const float*)d_in[7];
    const float* w_gcn = (const float*)d_in[8];
    const float* b_gcn = (const float*)d_in[9];
    const float* w_out = (const float*)d_in[10];
    const float* b_out = (const float*)d_in[11];
    float* out = (float*)d_out;

    int E = in_sizes[1] / 2;   // element count / 2 regardless of dtype width

    void *p_aln, *p_h, *p_gln, *p_xw;
    cudaGetSymbolAddress(&p_aln, g_aln);
    cudaGetSymbolAddress(&p_h,   g_h);
    cudaGetSymbolAddress(&p_gln, g_gln);
    cudaGetSymbolAddress(&p_xw,  g_xw);

    // 0. dtype detect (first 1024 index slots)
    k_detect<<<1, 256>>>((const unsigned int*)eidx, 1024);

    // 1. degree + dinv
    k_deg_init<<<(N_NODES + 255) / 256, 256>>>();
    k_deg_acc<<<(E + 255) / 256, 256>>>(eidx, E);
    k_dinv_fin<<<(N_NODES + 255) / 256, 256>>>();

    // 2. LN1
    k_ln128<<<(N_NODES * 32 + 255) / 256, 256>>>(x, ln1_g, ln1_b, (float*)p_aln);

    // 3. h = gelu(ln1 @ w_in^T + b_in)   [N,256]
    {
        dim3 grid((N_NODES + 127) / 128, FFN / 64);
        k_gemm<HIDDEN, 1><<<grid, 256>>>((const float*)p_aln, w_in, b_in,
                                         (float*)p_h, N_NODES, FFN);
    }

    // 4. LN2
    k_ln256<<<(N_NODES * 32 + 255) / 256, 256>>>((const float*)p_h, ln2_g, ln2_b,
                                                 (float*)p_gln);

    // 5. xw = gln @ w_gcn^T   [N,256] (no bias; added in agg init)
    {
        dim3 grid((N_NODES + 127) / 128, FFN / 64);
        k_gemm<FFN, 0><<<grid, 256>>>((const float*)p_gln, w_gcn, nullptr,
                                      (float*)p_xw, N_NODES, FFN);
    }

    // 6. agg = b_gcn + self-loop; then edge scatter
    k_agg_init<<<(N_NODES * (FFN / 4) + 255) / 256, 256>>>(b_gcn);
    k_scatter<<<((size_t)E * 32 + 255) / 256, 256>>>(eidx, E);

    // 7. hg = tanh(agg) * h  (into g_gln)
    k_combine<<<(N_NODES * (FFN / 4) + 255) / 256, 256>>>();

    // 8. out = hg @ w_out^T + b_out  [N,128]
    {
        dim3 grid((N_NODES + 127) / 128, HIDDEN / 64);
        k_gemm<FFN, 0><<<grid, 256>>>((const float*)p_gln, w_out, b_out,
                                      out, N_NODES, HIDDEN);
    }
}

// round 7
// speedup vs baseline: 1.1221x; 1.1221x over previous
#include <cuda_runtime.h>
#include <math.h>
#include <stdint.h>

#define N_NODES 50000
#define HIDDEN  128
#define FFN     256
#define LN_EPS  1e-5f
#define MAX_E   524288
#define NB_SCAN 196   // ceil(50000/256)

// ---------------- scratch (static device globals; no allocation) ----------
__device__ float  g_h  [(size_t)N_NODES * FFN];   // gelu(ln1(x) @ w_in^T + b_in)
__device__ float  g_xw [(size_t)N_NODES * FFN];   // ln2(h) @ w_gcn^T
__device__ float  g_hg [(size_t)N_NODES * FFN];   // tanh(agg) * h
__device__ float  g_dinv[N_NODES];
__device__ int    g_cnt [N_NODES];                // in-degree histogram
__device__ int    g_cur [N_NODES];                // fill cursors
__device__ int    g_rowptr[N_NODES + 1];
__device__ int    g_bsum[256];
__device__ int    g_boff[256];
__device__ int    g_csr [MAX_E];                  // src ids sorted by dst
__device__ float2 g_st1[N_NODES];                 // LN1 (mu, rstd) per row of x
__device__ float2 g_st2[N_NODES];                 // LN2 (mu, rstd) per row of h
__device__ int    g_is64;

// ---------------- dtype detect: int64 edge_index has zero high words -------
__global__ void k_detect(const unsigned int* __restrict__ w, int nslots) {
    __shared__ unsigned int red[256];
    unsigned int acc = 0;
    for (int i = threadIdx.x; i < nslots; i += blockDim.x) acc |= w[2 * i + 1];
    red[threadIdx.x] = acc;
    __syncthreads();
    for (int s = 128; s > 0; s >>= 1) {
        if (threadIdx.x < s) red[threadIdx.x] |= red[threadIdx.x + s];
        __syncthreads();
    }
    if (threadIdx.x == 0) g_is64 = (red[0] == 0u) ? 1 : 0;
}

// ---------------- CSR build -------------------------------------------------
__global__ void k_zero_cnt() {
    int i = blockIdx.x * blockDim.x + threadIdx.x;
    if (i < N_NODES) g_cnt[i] = 0;
}
__global__ void k_hist(const void* __restrict__ eidx, int E) {
    int e = blockIdx.x * blockDim.x + threadIdx.x;
    if (e >= E) return;
    int d = g_is64 ? (int)((const long long*)eidx)[E + e]
                   : ((const int*)eidx)[E + e];
    atomicAdd(&g_cnt[d], 1);
}
__global__ void k_scan1() {
    __shared__ int sh[256];
    int t = threadIdx.x;
    int i = blockIdx.x * 256 + t;
    int v = (i < N_NODES) ? g_cnt[i] : 0;
    sh[t] = v;
    __syncthreads();
    #pragma unroll
    for (int off = 1; off < 256; off <<= 1) {
        int addend = (t >= off) ? sh[t - off] : 0;
        __syncthreads();
        sh[t] += addend;
        __syncthreads();
    }
    if (i < N_NODES) g_rowptr[i] = sh[t] - v;   // exclusive
    if (t == 255) g_bsum[blockIdx.x] = sh[255];
}
__global__ void k_scan2() {
    __shared__ int sh[256];
    int t = threadIdx.x;
    int v = (t < NB_SCAN) ? g_bsum[t] : 0;
    sh[t] = v;
    __syncthreads();
    #pragma unroll
    for (int off = 1; off < 256; off <<= 1) {
        int addend = (t >= off) ? sh[t - off] : 0;
        __syncthreads();
        sh[t] += addend;
        __syncthreads();
    }
    g_boff[t] = sh[t] - v;   // exclusive
}
__global__ void k_scan3(int E) {
    int i = blockIdx.x * 256 + threadIdx.x;
    if (i < N_NODES) g_rowptr[i] += g_boff[blockIdx.x];
    if (i == 0) g_rowptr[N_NODES] = E;
}
// dinv = rsqrt(in_deg + 2)  (self-loop weight 2); also zero cursors
__global__ void k_dinv_cur() {
    int i = blockIdx.x * blockDim.x + threadIdx.x;
    if (i < N_NODES) {
        g_dinv[i] = rsqrtf((float)g_cnt[i] + 2.0f);
        g_cur[i] = 0;
    }
}
__global__ void k_fill(const void* __restrict__ eidx, int E) {
    int e = blockIdx.x * blockDim.x + threadIdx.x;
    if (e >= E) return;
    int s, d;
    if (g_is64) {
        const long long* p = (const long long*)eidx;
        s = (int)p[e]; d = (int)p[E + e];
    } else {
        const int* p = (const int*)eidx;
        s = p[e]; d = p[E + e];
    }
    int pos = g_rowptr[d] + atomicAdd(&g_cur[d], 1);
    g_csr[pos] = s;
}

// ---------------- LN row stats (warp per row) -------------------------------
template <int W>
__global__ void k_lnstats(const float* __restrict__ x, float2* __restrict__ st) {
    int warp = (blockIdx.x * blockDim.x + threadIdx.x) >> 5;
    if (warp >= N_NODES) return;
    int lane = threadIdx.x & 31;
    const float4* xr = (const float4*)(x + (size_t)warp * W);
    float s = 0.f, sq = 0.f;
    #pragma unroll
    for (int i = 0; i < W / 128; i++) {
        float4 v = xr[lane + i * 32];
        s  += v.x + v.y + v.z + v.w;
        sq += v.x * v.x + v.y * v.y + v.z * v.z + v.w * v.w;
    }
    #pragma unroll
    for (int o = 16; o; o >>= 1) {
        s  += __shfl_xor_sync(0xffffffffu, s,  o);
        sq += __shfl_xor_sync(0xffffffffu, sq, o);
    }
    if (lane == 0) {
        float mu  = s * (1.0f / W);
        float var = sq * (1.0f / W) - mu * mu;
        st[warp] = make_float2(mu, rsqrtf(var + LN_EPS));
    }
}

// ---------------- tf32 helpers ---------------------------------------------
__device__ __forceinline__ float f2tf32(float x) {
    unsigned r;
    asm("cvt.rna.tf32.f32 %0, %1;" : "=r"(r) : "f"(x));
    return __uint_as_float(r);
}
__device__ __forceinline__ void mma_tf32(float* c, const float* a, const float* b) {
    asm volatile(
        "mma.sync.aligned.m16n8k8.row.col.f32.tf32.tf32.f32 "
        "{%0,%1,%2,%3}, {%4,%5,%6,%7}, {%8,%9}, {%0,%1,%2,%3};"
        : "+f"(c[0]), "+f"(c[1]), "+f"(c[2]), "+f"(c[3])
        : "r"(__float_as_uint(a[0])), "r"(__float_as_uint(a[1])),
          "r"(__float_as_uint(a[2])), "r"(__float_as_uint(a[3])),
          "r"(__float_as_uint(b[0])), "r"(__float_as_uint(b[1])));
}

// EPI: 0 = bias only, 1 = gelu(x + bias)
template <int EPI>
__device__ __forceinline__ float epi_apply(float v) {
    if (EPI == 1) return 0.5f * v * (1.0f + erff(v * 0.70710678118654752f));
    return v;
}

// C[M,N] = LNopt(A)[M,K] @ W[N,K]^T (+bias) (+epilogue).
// BM=128, BN=64, BK=32, 256 threads, warp tile 32x32.
// LN!=0: A rows normalized on the fly using stats + lng/lnb.
template <int K, int EPI, int LN>
__global__ __launch_bounds__(256) void k_gemm(
    const float* __restrict__ A, const float* __restrict__ W,
    const float* __restrict__ bias, float* __restrict__ C, int M, int N,
    const float2* __restrict__ stats, const float* __restrict__ lng,
    const float* __restrict__ lnb) {
    const int BM = 128, BN = 64, BK = 32;
    __shared__ float As[BM][BK + 4];
    __shared__ float Bs[BK][BN + 8];
    int tid = threadIdx.x;
    int wid = tid >> 5, lane = tid & 31;
    int wm = wid >> 1, wn = wid & 1;
    int g = lane >> 2, tq = lane & 3;
    int bm0 = blockIdx.x * BM, bn0 = blockIdx.y * BN;

    float acc[2][4][4];
    #pragma unroll
    for (int mt = 0; mt < 2; mt++)
        #pragma unroll
        for (int nt = 0; nt < 4; nt++)
            #pragma unroll
            for (int i = 0; i < 4; i++) acc[mt][nt][i] = 0.0f;

    for (int k0 = 0; k0 < K; k0 += BK) {
        // A tile 128x32 (with optional fused LayerNorm)
        #pragma unroll
        for (int i = 0; i < 4; i++) {
            int idx = tid + i * 256;
            int row = idx >> 3, c4 = idx & 7;
            int gr = bm0 + row;
            float4 v = make_float4(0.f, 0.f, 0.f, 0.f);
            if (gr < M) {
                v = *(const float4*)(A + (size_t)gr * K + k0 + c4 * 4);
                if (LN) {
                    float2 st = stats[gr];
                    float4 gg = ((const float4*)lng)[k0 / 4 + c4];
                    float4 bb = ((const float4*)lnb)[k0 / 4 + c4];
                    v.x = (v.x - st.x) * st.y * gg.x + bb.x;
                    v.y = (v.y - st.x) * st.y * gg.y + bb.y;
                    v.z = (v.z - st.x) * st.y * gg.z + bb.z;
                    v.w = (v.w - st.x) * st.y * gg.w + bb.w;
                }
            }
            float* d = &As[row][c4 * 4];
            d[0] = f2tf32(v.x); d[1] = f2tf32(v.y);
            d[2] = f2tf32(v.z); d[3] = f2tf32(v.w);
        }
        // B tile (transpose W[n][k] -> Bs[k][n])
        #pragma unroll
        for (int i = 0; i < 2; i++) {
            int idx = tid + i * 256;
            int n = idx >> 3, c4 = idx & 7;
            float4 v = *(const float4*)(W + (size_t)(bn0 + n) * K + k0 + c4 * 4);
            Bs[c4 * 4 + 0][n] = f2tf32(v.x);
            Bs[c4 * 4 + 1][n] = f2tf32(v.y);
            Bs[c4 * 4 + 2][n] = f2tf32(v.z);
            Bs[c4 * 4 + 3][n] = f2tf32(v.w);
        }
        __syncthreads();
        #pragma unroll
        for (int ks = 0; ks < BK / 8; ks++) {
            float af[2][4], bf[4][2];
            #pragma unroll
            for (int mt = 0; mt < 2; mt++) {
                int rb = wm * 32 + mt * 16;
                af[mt][0] = As[rb + g    ][ks * 8 + tq];
                af[mt][1] = As[rb + g + 8][ks * 8 + tq];
                af[mt][2] = As[rb + g    ][ks * 8 + tq + 4];
                af[mt][3] = As[rb + g + 8][ks * 8 + tq + 4];
            }
            #pragma unroll
            for (int nt = 0; nt < 4; nt++) {
                int cb = wn * 32 + nt * 8;
                bf[nt][0] = Bs[ks * 8 + tq    ][cb + g];
                bf[nt][1] = Bs[ks * 8 + tq + 4][cb + g];
            }
            #pragma unroll
            for (int mt = 0; mt < 2; mt++)
                #pragma unroll
                for (int nt = 0; nt < 4; nt++)
                    mma_tf32(acc[mt][nt], af[mt], bf[nt]);
        }
        __syncthreads();
    }

    #pragma unroll
    for (int mt = 0; mt < 2; mt++) {
        int r0 = bm0 + wm * 32 + mt * 16 + g;
        #pragma unroll
        for (int nt = 0; nt < 4; nt++) {
            int c0 = bn0 + wn * 32 + nt * 8 + 2 * tq;
            float bv0 = bias ? bias[c0]     : 0.0f;
            float bv1 = bias ? bias[c0 + 1] : 0.0f;
            if (r0 < M) {
                C[(size_t)r0 * N + c0]     = epi_apply<EPI>(acc[mt][nt][0] + bv0);
                C[(size_t)r0 * N + c0 + 1] = epi_apply<EPI>(acc[mt][nt][1] + bv1);
            }
            if (r0 + 8 < M) {
                C[(size_t)(r0 + 8) * N + c0]     = epi_apply<EPI>(acc[mt][nt][2] + bv0);
                C[(size_t)(r0 + 8) * N + c0 + 1] = epi_apply<EPI>(acc[mt][nt][3] + bv1);
            }
        }
    }
}

// ---------------- fused GCN gather + gate ----------------------------------
// One warp per dst node:
//   acc = b_gcn + 2*dinv[d]^2 * xw[d] + sum_{e in CSR[d]} dinv[src]*dinv[d]*xw[src]
//   hg[d] = tanh(acc) * h[d]
__global__ __launch_bounds__(256) void k_gather(const float* __restrict__ bg) {
    int warp = (blockIdx.x * blockDim.x + threadIdx.x) >> 5;
    if (warp >= N_NODES) return;
    int lane = threadIdx.x & 31;

    float dvd = g_dinv[warp];
    float selfc = 2.0f * dvd * dvd;

    const float4* xwd = (const float4*)(g_xw + (size_t)warp * FFN);
    float4 b0 = ((const float4*)bg)[lane];
    float4 b1 = ((const float4*)bg)[lane + 32];
    float4 x0 = xwd[lane], x1 = xwd[lane + 32];
    float4 a0, a1;
    a0.x = b0.x + selfc * x0.x; a0.y = b0.y + selfc * x0.y;
    a0.z = b0.z + selfc * x0.z; a0.w = b0.w + selfc * x0.w;
    a1.x = b1.x + selfc * x1.x; a1.y = b1.y + selfc * x1.y;
    a1.z = b1.z + selfc * x1.z; a1.w = b1.w + selfc * x1.w;

    int e   = g_rowptr[warp];
    int end = g_rowptr[warp + 1];

    // 4-edge batches for MLP
    for (; e + 4 <= end; e += 4) {
        int s0 = g_csr[e], s1 = g_csr[e + 1], s2 = g_csr[e + 2], s3 = g_csr[e + 3];
        float c0 = g_dinv[s0] * dvd, c1 = g_dinv[s1] * dvd;
        float c2 = g_dinv[s2] * dvd, c3 = g_dinv[s3] * dvd;
        const float4* r0 = (const float4*)(g_xw + (size_t)s0 * FFN);
        const float4* r1 = (const float4*)(g_xw + (size_t)s1 * FFN);
        const float4* r2 = (const float4*)(g_xw + (size_t)s2 * FFN);
        const float4* r3 = (const float4*)(g_xw + (size_t)s3 * FFN);
        float4 v00 = r0[lane], v01 = r0[lane + 32];
        float4 v10 = r1[lane], v11 = r1[lane + 32];
        float4 v20 = r2[lane], v21 = r2[lane + 32];
        float4 v30 = r3[lane], v31 = r3[lane + 32];
        a0.x += c0 * v00.x + c1 * v10.x + c2 * v20.x + c3 * v30.x;
        a0.y += c0 * v00.y + c1 * v10.y + c2 * v20.y + c3 * v30.y;
        a0.z += c0 * v00.z + c1 * v10.z + c2 * v20.z + c3 * v30.z;
        a0.w += c0 * v00.w + c1 * v10.w + c2 * v20.w + c3 * v30.w;
        a1.x += c0 * v01.x + c1 * v11.x + c2 * v21.x + c3 * v31.x;
        a1.y += c0 * v01.y + c1 * v11.y + c2 * v21.y + c3 * v31.y;
        a1.z += c0 * v01.z + c1 * v11.z + c2 * v21.z + c3 * v31.z;
        a1.w += c0 * v01.w + c1 * v11.w + c2 * v21.w + c3 * v31.w;
    }
    for (; e < end; e++) {
        int s = g_csr[e];
        float c = g_dinv[s] * dvd;
        const float4* r = (const float4*)(g_xw + (size_t)s * FFN);
        float4 v0 = r[lane], v1 = r[lane + 32];
        a0.x += c * v0.x; a0.y += c * v0.y; a0.z += c * v0.z; a0.w += c * v0.w;
        a1.x += c * v1.x; a1.y += c * v1.y; a1.z += c * v1.z; a1.w += c * v1.w;
    }

    const float4* hd = (const float4*)(g_h + (size_t)warp * FFN);
    float4 h0 = hd[lane], h1 = hd[lane + 32];
    float4 o0, o1;
    o0.x = tanhf(a0.x) * h0.x; o0.y = tanhf(a0.y) * h0.y;
    o0.z = tanhf(a0.z) * h0.z; o0.w = tanhf(a0.w) * h0.w;
    o1.x = tanhf(a1.x) * h1.x; o1.y = tanhf(a1.y) * h1.y;
    o1.z = tanhf(a1.z) * h1.z; o1.w = tanhf(a1.w) * h1.w;
    float4* hg = (float4*)(g_hg + (size_t)warp * FFN);
    hg[lane] = o0;
    hg[lane + 32] = o1;
}

// ---------------- host ------------------------------------------------------
extern "C" void kernel_launch(void* const* d_in, const int* in_sizes, int n_in,
                              void* d_out, int out_size) {
    const float* x     = (const float*)d_in[0];
    const void*  eidx  = d_in[1];
    const float* ln1_g = (const float*)d_in[2];
    const float* ln1_b = (const float*)d_in[3];
    const float* w_in  = (const float*)d_in[4];
    const float* b_in  = (const float*)d_in[5];
    const float* ln2_g = (const float*)d_in[6];
    const float* ln2_b = (const float*)d_in[7];
    const float* w_gcn = (const float*)d_in[8];
    const float* b_gcn = (const float*)d_in[9];
    const float* w_out = (const float*)d_in[10];
    const float* b_out = (const float*)d_in[11];
    float* out = (float*)d_out;

    int E = in_sizes[1] / 2;

    void *p_h, *p_xw, *p_hg, *p_st1, *p_st2;
    cudaGetSymbolAddress(&p_h,   g_h);
    cudaGetSymbolAddress(&p_xw,  g_xw);
    cudaGetSymbolAddress(&p_hg,  g_hg);
    cudaGetSymbolAddress(&p_st1, g_st1);
    cudaGetSymbolAddress(&p_st2, g_st2);

    const int TB = 256;
    int nblk = (N_NODES + TB - 1) / TB;
    int eblk = (E + TB - 1) / TB;
    int wblk = (N_NODES * 32 + TB - 1) / TB;   // warp-per-node kernels

    // 0. dtype detect
    k_detect<<<1, 256>>>((const unsigned int*)eidx, 1024);

    // 1. CSR build + dinv
    k_zero_cnt<<<nblk, TB>>>();
    k_hist<<<eblk, TB>>>(eidx, E);
    k_scan1<<<NB_SCAN, 256>>>();
    k_scan2<<<1, 256>>>();
    k_scan3<<<NB_SCAN, 256>>>(E);
    k_dinv_cur<<<nblk, TB>>>();
    k_fill<<<eblk, TB>>>(eidx, E);

    // 2. LN1 stats; GEMM1 (fused LN1 + GELU): x -> h
    k_lnstats<HIDDEN><<<wblk, TB>>>(x, (float2*)p_st1);
    {
        dim3 grid((N_NODES + 127) / 128, FFN / 64);
        k_gemm<HIDDEN, 1, 1><<<grid, 256>>>(x, w_in, b_in, (float*)p_h,
                                            N_NODES, FFN,
                                            (const float2*)p_st1, ln1_g, ln1_b);
    }

    // 3. LN2 stats; GEMM2 (fused LN2): h -> xw
    k_lnstats<FFN><<<wblk, TB>>>((const float*)p_h, (float2*)p_st2);
    {
        dim3 grid((N_NODES + 127) / 128, FFN / 64);
        k_gemm<FFN, 0, 1><<<grid, 256>>>((const float*)p_h, w_gcn, nullptr,
                                         (float*)p_xw, N_NODES, FFN,
                                         (const float2*)p_st2, ln2_g, ln2_b);
    }

    // 4. fused gather + self-loop + bias + tanh-gate: -> hg
    k_gather<<<wblk, TB>>>(b_gcn);

    // 5. GEMM3: hg -> out
    {
        dim3 grid((N_NODES + 127) / 128, HIDDEN / 64);
        k_gemm<FFN, 0, 0><<<grid, 256>>>((const float*)p_hg, w_out, b_out,
                                         out, N_NODES, HIDDEN,
                                         nullptr, nullptr, nullptr);
    }
}

// round 8
// speedup vs baseline: 1.4465x; 1.2891x over previous
#include <cuda_runtime.h>
#include <cuda_bf16.h>
#include <math.h>
#include <stdint.h>

#define N_NODES 50000
#define HIDDEN  128
#define FFN     256
#define LN_EPS  1e-5f
#define MAX_E   524288
#define NB_SCAN 196   // ceil(50000/256)

// ---------------- scratch (static device globals; no allocation) ----------
__device__ __align__(16) float g_h [(size_t)N_NODES * FFN];   // gelu(ln1(x)@w_in^T+b_in)
__device__ __align__(16) __nv_bfloat16 g_xw[(size_t)N_NODES * FFN]; // ln2(h)@w_gcn^T (bf16)
__device__ __align__(16) float g_hg[(size_t)N_NODES * FFN];   // tanh(agg)*h
__device__ float  g_dinv[N_NODES];
__device__ int    g_cnt [N_NODES];
__device__ int    g_cur [N_NODES];
__device__ int    g_rowptr[N_NODES + 1];
__device__ int    g_bsum[256];
__device__ int    g_boff[256];
__device__ int    g_csr [MAX_E];
__device__ float2 g_st1[N_NODES];
__device__ float2 g_st2[N_NODES];
__device__ int    g_is64;

// ---------------- dtype detect: int64 edge_index has zero high words -------
__global__ void k_detect(const unsigned int* __restrict__ w, int nslots) {
    __shared__ unsigned int red[256];
    unsigned int acc = 0;
    for (int i = threadIdx.x; i < nslots; i += blockDim.x) acc |= w[2 * i + 1];
    red[threadIdx.x] = acc;
    __syncthreads();
    for (int s = 128; s > 0; s >>= 1) {
        if (threadIdx.x < s) red[threadIdx.x] |= red[threadIdx.x + s];
        __syncthreads();
    }
    if (threadIdx.x == 0) g_is64 = (red[0] == 0u) ? 1 : 0;
}

// ---------------- CSR build -------------------------------------------------
__global__ void k_zero_cnt() {
    int i = blockIdx.x * blockDim.x + threadIdx.x;
    if (i < N_NODES) g_cnt[i] = 0;
}
__global__ void k_hist(const void* __restrict__ eidx, int E) {
    int e = blockIdx.x * blockDim.x + threadIdx.x;
    if (e >= E) return;
    int d = g_is64 ? (int)((const long long*)eidx)[E + e]
                   : ((const int*)eidx)[E + e];
    atomicAdd(&g_cnt[d], 1);
}
__global__ void k_scan1() {
    __shared__ int sh[256];
    int t = threadIdx.x;
    int i = blockIdx.x * 256 + t;
    int v = (i < N_NODES) ? g_cnt[i] : 0;
    sh[t] = v;
    __syncthreads();
    #pragma unroll
    for (int off = 1; off < 256; off <<= 1) {
        int addend = (t >= off) ? sh[t - off] : 0;
        __syncthreads();
        sh[t] += addend;
        __syncthreads();
    }
    if (i < N_NODES) g_rowptr[i] = sh[t] - v;
    if (t == 255) g_bsum[blockIdx.x] = sh[255];
}
__global__ void k_scan2() {
    __shared__ int sh[256];
    int t = threadIdx.x;
    int v = (t < NB_SCAN) ? g_bsum[t] : 0;
    sh[t] = v;
    __syncthreads();
    #pragma unroll
    for (int off = 1; off < 256; off <<= 1) {
        int addend = (t >= off) ? sh[t - off] : 0;
        __syncthreads();
        sh[t] += addend;
        __syncthreads();
    }
    g_boff[t] = sh[t] - v;
}
__global__ void k_scan3(int E) {
    int i = blockIdx.x * 256 + threadIdx.x;
    if (i < N_NODES) g_rowptr[i] += g_boff[blockIdx.x];
    if (i == 0) g_rowptr[N_NODES] = E;
}
__global__ void k_dinv_cur() {
    int i = blockIdx.x * blockDim.x + threadIdx.x;
    if (i < N_NODES) {
        g_dinv[i] = rsqrtf((float)g_cnt[i] + 2.0f);
        g_cur[i] = 0;
    }
}
__global__ void k_fill(const void* __restrict__ eidx, int E) {
    int e = blockIdx.x * blockDim.x + threadIdx.x;
    if (e >= E) return;
    int s, d;
    if (g_is64) {
        const long long* p = (const long long*)eidx;
        s = (int)p[e]; d = (int)p[E + e];
    } else {
        const int* p = (const int*)eidx;
        s = p[e]; d = p[E + e];
    }
    int pos = g_rowptr[d] + atomicAdd(&g_cur[d], 1);
    g_csr[pos] = s;
}

// ---------------- LN row stats (warp per row) -------------------------------
template <int W>
__global__ void k_lnstats(const float* __restrict__ x, float2* __restrict__ st) {
    int warp = (blockIdx.x * blockDim.x + threadIdx.x) >> 5;
    if (warp >= N_NODES) return;
    int lane = threadIdx.x & 31;
    const float4* xr = (const float4*)(x + (size_t)warp * W);
    float s = 0.f, sq = 0.f;
    #pragma unroll
    for (int i = 0; i < W / 128; i++) {
        float4 v = xr[lane + i * 32];
        s  += v.x + v.y + v.z + v.w;
        sq += v.x * v.x + v.y * v.y + v.z * v.z + v.w * v.w;
    }
    #pragma unroll
    for (int o = 16; o; o >>= 1) {
        s  += __shfl_xor_sync(0xffffffffu, s,  o);
        sq += __shfl_xor_sync(0xffffffffu, sq, o);
    }
    if (lane == 0) {
        float mu  = s * (1.0f / W);
        float var = sq * (1.0f / W) - mu * mu;
        st[warp] = make_float2(mu, rsqrtf(var + LN_EPS));
    }
}

// ---------------- mma helpers ----------------------------------------------
__device__ __forceinline__ float f2tf32(float x) {
    unsigned r;
    asm("cvt.rna.tf32.f32 %0, %1;" : "=r"(r) : "f"(x));
    return __uint_as_float(r);
}
__device__ __forceinline__ void mma_tf32(float* c, const float* a, const float* b) {
    asm volatile(
        "mma.sync.aligned.m16n8k8.row.col.f32.tf32.tf32.f32 "
        "{%0,%1,%2,%3}, {%4,%5,%6,%7}, {%8,%9}, {%0,%1,%2,%3};"
        : "+f"(c[0]), "+f"(c[1]), "+f"(c[2]), "+f"(c[3])
        : "r"(__float_as_uint(a[0])), "r"(__float_as_uint(a[1])),
          "r"(__float_as_uint(a[2])), "r"(__float_as_uint(a[3])),
          "r"(__float_as_uint(b[0])), "r"(__float_as_uint(b[1])));
}
__device__ __forceinline__ void mma_bf16(float* c, const unsigned* a, const unsigned* b) {
    asm volatile(
        "mma.sync.aligned.m16n8k16.row.col.f32.bf16.bf16.f32 "
        "{%0,%1,%2,%3}, {%4,%5,%6,%7}, {%8,%9}, {%0,%1,%2,%3};"
        : "+f"(c[0]), "+f"(c[1]), "+f"(c[2]), "+f"(c[3])
        : "r"(a[0]), "r"(a[1]), "r"(a[2]), "r"(a[3]), "r"(b[0]), "r"(b[1]));
}
// pack: lo = a (even k/col), hi = b
__device__ __forceinline__ unsigned pack_bf16(float a, float b) {
    unsigned r;
    asm("cvt.rn.bf16x2.f32 %0, %1, %2;" : "=r"(r) : "f"(b), "f"(a));
    return r;
}

template <int EPI>
__device__ __forceinline__ float epi_apply(float v) {
    if (EPI == 1) return 0.5f * v * (1.0f + erff(v * 0.70710678118654752f));
    return v;
}

// ============================================================================
// tf32 GEMM: C[M,N] = LNopt(A)[M,K] @ W[N,K]^T (+bias)(+gelu)
// BM=128, BN=128, BK=32, 256 threads, warp tile 32x64 (4x2 warp grid).
// Register-staged global prefetch; A and W both row-major in smem, pitch 36.
// ============================================================================
template <int K, int EPI, int LN>
__global__ __launch_bounds__(256) void k_gemm_tf32(
    const float* __restrict__ A, const float* __restrict__ W,
    const float* __restrict__ bias, float* __restrict__ C, int M, int N,
    const float2* __restrict__ stats, const float* __restrict__ lng,
    const float* __restrict__ lnb) {
    const int BK = 32, PITCH = 36;
    __shared__ float As[128 * PITCH];
    __shared__ float Bs[128 * PITCH];
    int tid = threadIdx.x;
    int wid = tid >> 5, lane = tid & 31;
    int wm = wid >> 1, wn = wid & 1;
    int g = lane >> 2, tq = lane & 3;
    int bm0 = blockIdx.x * 128, bn0 = blockIdx.y * 128;

    float acc[2][8][4];
    #pragma unroll
    for (int mt = 0; mt < 2; mt++)
        #pragma unroll
        for (int nt = 0; nt < 8; nt++)
            #pragma unroll
            for (int i = 0; i < 4; i++) acc[mt][nt][i] = 0.0f;

    int lrow = tid >> 3, lc4 = tid & 7;          // 32 rows per pass, 4 passes
    float4 ar[4], br[4];

    // prologue load k0 = 0
    #pragma unroll
    for (int i = 0; i < 4; i++) {
        int row = lrow + i * 32;
        int gr = bm0 + row;
        float4 v = make_float4(0.f, 0.f, 0.f, 0.f);
        if (gr < M) {
            v = *(const float4*)(A + (size_t)gr * K + lc4 * 4);
            if (LN) {
                float2 st = stats[gr];
                float4 gg = ((const float4*)lng)[lc4];
                float4 bb = ((const float4*)lnb)[lc4];
                v.x = (v.x - st.x) * st.y * gg.x + bb.x;
                v.y = (v.y - st.x) * st.y * gg.y + bb.y;
                v.z = (v.z - st.x) * st.y * gg.z + bb.z;
                v.w = (v.w - st.x) * st.y * gg.w + bb.w;
            }
        }
        ar[i] = v;
        br[i] = *(const float4*)(W + (size_t)(bn0 + row) * K + lc4 * 4);
    }

    #pragma unroll 1
    for (int k0 = 0; k0 < K; k0 += BK) {
        // STS current tiles
        #pragma unroll
        for (int i = 0; i < 4; i++) {
            int row = lrow + i * 32;
            float* da = &As[row * PITCH + lc4 * 4];
            da[0] = f2tf32(ar[i].x); da[1] = f2tf32(ar[i].y);
            da[2] = f2tf32(ar[i].z); da[3] = f2tf32(ar[i].w);
            float* db = &Bs[row * PITCH + lc4 * 4];
            db[0] = f2tf32(br[i].x); db[1] = f2tf32(br[i].y);
            db[2] = f2tf32(br[i].z); db[3] = f2tf32(br[i].w);
        }
        __syncthreads();

        // prefetch next k-tile into registers
        if (k0 + BK < K) {
            int kn = k0 + BK;
            #pragma unroll
            for (int i = 0; i < 4; i++) {
                int row = lrow + i * 32;
                int gr = bm0 + row;
                float4 v = make_float4(0.f, 0.f, 0.f, 0.f);
                if (gr < M) {
                    v = *(const float4*)(A + (size_t)gr * K + kn + lc4 * 4);
                    if (LN) {
                        float2 st = stats[gr];
                        float4 gg = ((const float4*)lng)[kn / 4 + lc4];
                        float4 bb = ((const float4*)lnb)[kn / 4 + lc4];
                        v.x = (v.x - st.x) * st.y * gg.x + bb.x;
                        v.y = (v.y - st.x) * st.y * gg.y + bb.y;
                        v.z = (v.z - st.x) * st.y * gg.z + bb.z;
                        v.w = (v.w - st.x) * st.y * gg.w + bb.w;
                    }
                }
                ar[i] = v;
                br[i] = *(const float4*)(W + (size_t)(bn0 + row) * K + kn + lc4 * 4);
            }
        }

        // compute
        #pragma unroll
        for (int ks = 0; ks < 4; ks++) {
            int k8 = ks * 8;
            float af[2][4], bfv[8][2];
            #pragma unroll
            for (int mt = 0; mt < 2; mt++) {
                int rb = wm * 32 + mt * 16;
                af[mt][0] = As[(rb + g    ) * PITCH + k8 + tq];
                af[mt][1] = As[(rb + g + 8) * PITCH + k8 + tq];
                af[mt][2] = As[(rb + g    ) * PITCH + k8 + tq + 4];
                af[mt][3] = As[(rb + g + 8) * PITCH + k8 + tq + 4];
            }
            #pragma unroll
            for (int nt = 0; nt < 8; nt++) {
                int cb = wn * 64 + nt * 8;
                bfv[nt][0] = Bs[(cb + g) * PITCH + k8 + tq];
                bfv[nt][1] = Bs[(cb + g) * PITCH + k8 + tq + 4];
            }
            #pragma unroll
            for (int mt = 0; mt < 2; mt++)
                #pragma unroll
                for (int nt = 0; nt < 8; nt++)
                    mma_tf32(acc[mt][nt], af[mt], bfv[nt]);
        }
        __syncthreads();
    }

    // epilogue
    #pragma unroll
    for (int mt = 0; mt < 2; mt++) {
        int r0 = bm0 + wm * 32 + mt * 16 + g;
        #pragma unroll
        for (int nt = 0; nt < 8; nt++) {
            int c0 = bn0 + wn * 64 + nt * 8 + 2 * tq;
            float bv0 = bias ? bias[c0]     : 0.0f;
            float bv1 = bias ? bias[c0 + 1] : 0.0f;
            if (r0 < M) {
                C[(size_t)r0 * N + c0]     = epi_apply<EPI>(acc[mt][nt][0] + bv0);
                C[(size_t)r0 * N + c0 + 1] = epi_apply<EPI>(acc[mt][nt][1] + bv1);
            }
            if (r0 + 8 < M) {
                C[(size_t)(r0 + 8) * N + c0]     = epi_apply<EPI>(acc[mt][nt][2] + bv0);
                C[(size_t)(r0 + 8) * N + c0 + 1] = epi_apply<EPI>(acc[mt][nt][3] + bv1);
            }
        }
    }
}

// ============================================================================
// bf16 GEMM (GEMM2): xw_bf16[M,N] = LN2(A)[M,K] @ W[N,K]^T    K=N=256
// Same tiling; smem holds packed bf16x2 words, pitch 20 u32 per row.
// ============================================================================
template <int K>
__global__ __launch_bounds__(256) void k_gemm_bf16(
    const float* __restrict__ A, const float* __restrict__ W,
    __nv_bfloat16* __restrict__ C, int M, int N,
    const float2* __restrict__ stats, const float* __restrict__ lng,
    const float* __restrict__ lnb) {
    const int BK = 32, PITCH = 20;   // u32 words per row (16 data + 4 pad)
    __shared__ unsigned As[128 * PITCH];
    __shared__ unsigned Bs[128 * PITCH];
    int tid = threadIdx.x;
    int wid = tid >> 5, lane = tid & 31;
    int wm = wid >> 1, wn = wid & 1;
    int g = lane >> 2, tq = lane & 3;
    int bm0 = blockIdx.x * 128, bn0 = blockIdx.y * 128;

    float acc[2][8][4];
    #pragma unroll
    for (int mt = 0; mt < 2; mt++)
        #pragma unroll
        for (int nt = 0; nt < 8; nt++)
            #pragma unroll
            for (int i = 0; i < 4; i++) acc[mt][nt][i] = 0.0f;

    int lrow = tid >> 3, lc4 = tid & 7;
    float4 ar[4], br[4];

    #pragma unroll
    for (int i = 0; i < 4; i++) {
        int row = lrow + i * 32;
        int gr = bm0 + row;
        float4 v = make_float4(0.f, 0.f, 0.f, 0.f);
        if (gr < M) {
            v = *(const float4*)(A + (size_t)gr * K + lc4 * 4);
            float2 st = stats[gr];
            float4 gg = ((const float4*)lng)[lc4];
            float4 bb = ((const float4*)lnb)[lc4];
            v.x = (v.x - st.x) * st.y * gg.x + bb.x;
            v.y = (v.y - st.x) * st.y * gg.y + bb.y;
            v.z = (v.z - st.x) * st.y * gg.z + bb.z;
            v.w = (v.w - st.x) * st.y * gg.w + bb.w;
        }
        ar[i] = v;
        br[i] = *(const float4*)(W + (size_t)(bn0 + row) * K + lc4 * 4);
    }

    #pragma unroll 1
    for (int k0 = 0; k0 < K; k0 += BK) {
        #pragma unroll
        for (int i = 0; i < 4; i++) {
            int row = lrow + i * 32;
            As[row * PITCH + lc4 * 2]     = pack_bf16(ar[i].x, ar[i].y);
            As[row * PITCH + lc4 * 2 + 1] = pack_bf16(ar[i].z, ar[i].w);
            Bs[row * PITCH + lc4 * 2]     = pack_bf16(br[i].x, br[i].y);
            Bs[row * PITCH + lc4 * 2 + 1] = pack_bf16(br[i].z, br[i].w);
        }
        __syncthreads();

        if (k0 + BK < K) {
            int kn = k0 + BK;
            #pragma unroll
            for (int i = 0; i < 4; i++) {
                int row = lrow + i * 32;
                int gr = bm0 + row;
                float4 v = make_float4(0.f, 0.f, 0.f, 0.f);
                if (gr < M) {
                    v = *(const float4*)(A + (size_t)gr * K + kn + lc4 * 4);
                    float2 st = stats[gr];
                    float4 gg = ((const float4*)lng)[kn / 4 + lc4];
                    float4 bb = ((const float4*)lnb)[kn / 4 + lc4];
                    v.x = (v.x - st.x) * st.y * gg.x + bb.x;
                    v.y = (v.y - st.x) * st.y * gg.y + bb.y;
                    v.z = (v.z - st.x) * st.y * gg.z + bb.z;
                    v.w = (v.w - st.x) * st.y * gg.w + bb.w;
                }
                ar[i] = v;
                br[i] = *(const float4*)(W + (size_t)(bn0 + row) * K + kn + lc4 * 4);
            }
        }

        #pragma unroll
        for (int ks = 0; ks < 2; ks++) {     // k16 per mma
            int k8 = ks * 8;
            unsigned af[2][4], bfv[8][2];
            #pragma unroll
            for (int mt = 0; mt < 2; mt++) {
                int rb = wm * 32 + mt * 16;
                af[mt][0] = As[(rb + g    ) * PITCH + k8 + tq];
                af[mt][1] = As[(rb + g + 8) * PITCH + k8 + tq];
                af[mt][2] = As[(rb + g    ) * PITCH + k8 + tq + 4];
                af[mt][3] = As[(rb + g + 8) * PITCH + k8 + tq + 4];
            }
            #pragma unroll
            for (int nt = 0; nt < 8; nt++) {
                int cb = wn * 64 + nt * 8;
                bfv[nt][0] = Bs[(cb + g) * PITCH + k8 + tq];
                bfv[nt][1] = Bs[(cb + g) * PITCH + k8 + tq + 4];
            }
            #pragma unroll
            for (int mt = 0; mt < 2; mt++)
                #pragma unroll
                for (int nt = 0; nt < 8; nt++)
                    mma_bf16(acc[mt][nt], af[mt], bfv[nt]);
        }
        __syncthreads();
    }

    // epilogue: store bf16 pairs
    #pragma unroll
    for (int mt = 0; mt < 2; mt++) {
        int r0 = bm0 + wm * 32 + mt * 16 + g;
        #pragma unroll
        for (int nt = 0; nt < 8; nt++) {
            int c0 = bn0 + wn * 64 + nt * 8 + 2 * tq;
            if (r0 < M)
                *(unsigned*)(C + (size_t)r0 * N + c0) = pack_bf16(acc[mt][nt][0], acc[mt][nt][1]);
            if (r0 + 8 < M)
                *(unsigned*)(C + (size_t)(r0 + 8) * N + c0) = pack_bf16(acc[mt][nt][2], acc[mt][nt][3]);
        }
    }
}

// ---------------- fused GCN gather + gate (bf16 xw) -------------------------
// warp per dst node; lane owns 8 channels (one uint4 of bf16 per row).
__global__ __launch_bounds__(256) void k_gather(const float* __restrict__ bg) {
    int warp = (blockIdx.x * blockDim.x + threadIdx.x) >> 5;
    if (warp >= N_NODES) return;
    int lane = threadIdx.x & 31;

    float dvd = g_dinv[warp];
    float selfc = 2.0f * dvd * dvd;

    float a[8];
    {
        float4 b0 = ((const float4*)bg)[2 * lane];
        float4 b1 = ((const float4*)bg)[2 * lane + 1];
        uint4 q = ((const uint4*)(g_xw + (size_t)warp * FFN))[lane];
        const __nv_bfloat162* p = (const __nv_bfloat162*)&q;
        float2 v0 = __bfloat1622float2(p[0]);
        float2 v1 = __bfloat1622float2(p[1]);
        float2 v2 = __bfloat1622float2(p[2]);
        float2 v3 = __bfloat1622float2(p[3]);
        a[0] = b0.x + selfc * v0.x; a[1] = b0.y + selfc * v0.y;
        a[2] = b0.z + selfc * v1.x; a[3] = b0.w + selfc * v1.y;
        a[4] = b1.x + selfc * v2.x; a[5] = b1.y + selfc * v2.y;
        a[6] = b1.z + selfc * v3.x; a[7] = b1.w + selfc * v3.y;
    }

    int e   = g_rowptr[warp];
    int end = g_rowptr[warp + 1];

    for (; e + 4 <= end; e += 4) {
        int s0 = g_csr[e], s1 = g_csr[e + 1], s2 = g_csr[e + 2], s3 = g_csr[e + 3];
        float c0 = g_dinv[s0] * dvd, c1 = g_dinv[s1] * dvd;
        float c2 = g_dinv[s2] * dvd, c3 = g_dinv[s3] * dvd;
        uint4 q0 = ((const uint4*)(g_xw + (size_t)s0 * FFN))[lane];
        uint4 q1 = ((const uint4*)(g_xw + (size_t)s1 * FFN))[lane];
        uint4 q2 = ((const uint4*)(g_xw + (size_t)s2 * FFN))[lane];
        uint4 q3 = ((const uint4*)(g_xw + (size_t)s3 * FFN))[lane];
        #pragma unroll
        for (int j = 0; j < 4; j++) {
            float2 w0 = __bfloat1622float2(((const __nv_bfloat162*)&q0)[j]);
            float2 w1 = __bfloat1622float2(((const __nv_bfloat162*)&q1)[j]);
            float2 w2 = __bfloat1622float2(((const __nv_bfloat162*)&q2)[j]);
            float2 w3 = __bfloat1622float2(((const __nv_bfloat162*)&q3)[j]);
            a[2*j]   += c0 * w0.x + c1 * w1.x + c2 * w2.x + c3 * w3.x;
            a[2*j+1] += c0 * w0.y + c1 * w1.y + c2 * w2.y + c3 * w3.y;
        }
    }
    for (; e < end; e++) {
        int s = g_csr[e];
        float c = g_dinv[s] * dvd;
        uint4 q = ((const uint4*)(g_xw + (size_t)s * FFN))[lane];
        #pragma unroll
        for (int j = 0; j < 4; j++) {
            float2 w = __bfloat1622float2(((const __nv_bfloat162*)&q)[j]);
            a[2*j]   += c * w.x;
            a[2*j+1] += c * w.y;
        }
    }

    const float4* hd = (const float4*)(g_h + (size_t)warp * FFN);
    float4* hgd = (float4*)(g_hg + (size_t)warp * FFN);
    #pragma unroll
    for (int j = 0; j < 2; j++) {
        float4 h = hd[2 * lane + j];
        float4 o;
        o.x = tanhf(a[4*j + 0]) * h.x;
        o.y = tanhf(a[4*j + 1]) * h.y;
        o.z = tanhf(a[4*j + 2]) * h.z;
        o.w = tanhf(a[4*j + 3]) * h.w;
        hgd[2 * lane + j] = o;
    }
}

// ---------------- host ------------------------------------------------------
extern "C" void kernel_launch(void* const* d_in, const int* in_sizes, int n_in,
                              void* d_out, int out_size) {
    const float* x     = (const float*)d_in[0];
    const void*  eidx  = d_in[1];
    const float* ln1_g = (const float*)d_in[2];
    const float* ln1_b = (const float*)d_in[3];
    const float* w_in  = (const float*)d_in[4];
    const float* b_in  = (const float*)d_in[5];
    const float* ln2_g = (const float*)d_in[6];
    const float* ln2_b = (const float*)d_in[7];
    const float* w_gcn = (const float*)d_in[8];
    const float* b_gcn = (const float*)d_in[9];
    const float* w_out = (const float*)d_in[10];
    const float* b_out = (const float*)d_in[11];
    float* out = (float*)d_out;

    int E = in_sizes[1] / 2;

    void *p_h, *p_xw, *p_hg, *p_st1, *p_st2;
    cudaGetSymbolAddress(&p_h,   g_h);
    cudaGetSymbolAddress(&p_xw,  g_xw);
    cudaGetSymbolAddress(&p_hg,  g_hg);
    cudaGetSymbolAddress(&p_st1, g_st1);
    cudaGetSymbolAddress(&p_st2, g_st2);

    const int TB = 256;
    int nblk = (N_NODES + TB - 1) / TB;
    int eblk = (E + TB - 1) / TB;
    int wblk = (N_NODES * 32 + TB - 1) / TB;

    // 0. dtype detect
    k_detect<<<1, 256>>>((const unsigned int*)eidx, 1024);

    // 1. CSR build + dinv
    k_zero_cnt<<<nblk, TB>>>();
    k_hist<<<eblk, TB>>>(eidx, E);
    k_scan1<<<NB_SCAN, 256>>>();
    k_scan2<<<1, 256>>>();
    k_scan3<<<NB_SCAN, 256>>>(E);
    k_dinv_cur<<<nblk, TB>>>();
    k_fill<<<eblk, TB>>>(eidx, E);

    // 2. LN1 stats; GEMM1 (fused LN1 + GELU): x -> h   [tf32]
    k_lnstats<HIDDEN><<<wblk, TB>>>(x, (float2*)p_st1);
    {
        dim3 grid((N_NODES + 127) / 128, FFN / 128);
        k_gemm_tf32<HIDDEN, 1, 1><<<grid, 256>>>(x, w_in, b_in, (float*)p_h,
                                                 N_NODES, FFN,
                                                 (const float2*)p_st1, ln1_g, ln1_b);
    }

    // 3. LN2 stats; GEMM2 (fused LN2): h -> xw (bf16)  [bf16 mma]
    k_lnstats<FFN><<<wblk, TB>>>((const float*)p_h, (float2*)p_st2);
    {
        dim3 grid((N_NODES + 127) / 128, FFN / 128);
        k_gemm_bf16<FFN><<<grid, 256>>>((const float*)p_h, w_gcn,
                                        (__nv_bfloat16*)p_xw, N_NODES, FFN,
                                        (const float2*)p_st2, ln2_g, ln2_b);
    }

    // 4. fused gather + self-loop + bias + tanh-gate: -> hg
    k_gather<<<wblk, TB>>>(b_gcn);

    // 5. GEMM3: hg -> out   [tf32]
    {
        dim3 grid((N_NODES + 127) / 128, HIDDEN / 128);
        k_gemm_tf32<FFN, 0, 0><<<grid, 256>>>((const float*)p_hg, w_out, b_out,
                                              out, N_NODES, HIDDEN,
                                              nullptr, nullptr, nullptr);
    }
}

// round 9
// speedup vs baseline: 1.4474x; 1.0006x over previous
#include <cuda_runtime.h>
#include <cuda_bf16.h>
#include <math.h>
#include <stdint.h>

#define N_NODES 50000
#define HIDDEN  128
#define FFN     256
#define LN_EPS  1e-5f
#define MAX_E   524288
#define NB_SCAN 196   // ceil(50000/256)

// ---------------- scratch (static device globals; no allocation) ----------
__device__ __align__(16) float g_h [(size_t)N_NODES * FFN];
__device__ __align__(16) __nv_bfloat16 g_xw[(size_t)N_NODES * FFN];
__device__ __align__(16) float g_hg[(size_t)N_NODES * FFN];
__device__ float  g_dinv[N_NODES];
__device__ int    g_cnt [N_NODES];
__device__ int    g_cur [N_NODES];
__device__ int    g_rowptr[N_NODES + 1];
__device__ int    g_bsum[256];
__device__ int    g_csr [MAX_E];
__device__ float2 g_st1[N_NODES];
__device__ float2 g_st2[N_NODES];
__device__ int    g_is64;

// ---------------- init: zero histogram + dtype detect (block 0) -------------
__global__ void k_init(const unsigned int* __restrict__ w, int nslots) {
    int i = blockIdx.x * blockDim.x + threadIdx.x;
    if (i < N_NODES) g_cnt[i] = 0;
    if (blockIdx.x == 0) {
        __shared__ unsigned int red[256];
        unsigned int acc = 0;
        for (int j = threadIdx.x; j < nslots; j += blockDim.x) acc |= w[2 * j + 1];
        red[threadIdx.x] = acc;
        __syncthreads();
        for (int s = 128; s > 0; s >>= 1) {
            if (threadIdx.x < s) red[threadIdx.x] |= red[threadIdx.x + s];
            __syncthreads();
        }
        if (threadIdx.x == 0) g_is64 = (red[0] == 0u) ? 1 : 0;
    }
}

// ---------------- CSR build -------------------------------------------------
__global__ void k_hist(const void* __restrict__ eidx, int E) {
    int e = blockIdx.x * blockDim.x + threadIdx.x;
    if (e >= E) return;
    int d = g_is64 ? (int)((const long long*)eidx)[E + e]
                   : ((const int*)eidx)[E + e];
    atomicAdd(&g_cnt[d], 1);
}
__global__ void k_scan1() {
    __shared__ int sh[256];
    int t = threadIdx.x;
    int i = blockIdx.x * 256 + t;
    int v = (i < N_NODES) ? g_cnt[i] : 0;
    sh[t] = v;
    __syncthreads();
    #pragma unroll
    for (int off = 1; off < 256; off <<= 1) {
        int addend = (t >= off) ? sh[t - off] : 0;
        __syncthreads();
        sh[t] += addend;
        __syncthreads();
    }
    if (i < N_NODES) g_rowptr[i] = sh[t] - v;   // block-local exclusive
    if (t == 255) g_bsum[blockIdx.x] = sh[255];
}
// scan block sums locally (196 entries), add offset, init dinv + cursors
__global__ void k_scan3(int E) {
    __shared__ int sh[256];
    int t = threadIdx.x;
    int v = (t < NB_SCAN) ? g_bsum[t] : 0;
    sh[t] = v;
    __syncthreads();
    #pragma unroll
    for (int off = 1; off < 256; off <<= 1) {
        int addend = (t >= off) ? sh[t - off] : 0;
        __syncthreads();
        sh[t] += addend;
        __syncthreads();
    }
    int boff = (blockIdx.x > 0) ? sh[blockIdx.x - 1] : 0;  // exclusive
    int i = blockIdx.x * 256 + t;
    if (i < N_NODES) {
        g_rowptr[i] += boff;
        g_dinv[i] = rsqrtf((float)g_cnt[i] + 2.0f);
        g_cur[i] = 0;
    }
    if (i == 0) g_rowptr[N_NODES] = E;
}
__global__ void k_fill(const void* __restrict__ eidx, int E) {
    int e = blockIdx.x * blockDim.x + threadIdx.x;
    if (e >= E) return;
    int s, d;
    if (g_is64) {
        const long long* p = (const long long*)eidx;
        s = (int)p[e]; d = (int)p[E + e];
    } else {
        const int* p = (const int*)eidx;
        s = p[e]; d = p[E + e];
    }
    int pos = g_rowptr[d] + atomicAdd(&g_cur[d], 1);
    g_csr[pos] = s;
}

// ---------------- LN row stats (warp per row) -------------------------------
template <int W>
__global__ void k_lnstats(const float* __restrict__ x, float2* __restrict__ st) {
    int warp = (blockIdx.x * blockDim.x + threadIdx.x) >> 5;
    if (warp >= N_NODES) return;
    int lane = threadIdx.x & 31;
    const float4* xr = (const float4*)(x + (size_t)warp * W);
    float s = 0.f, sq = 0.f;
    #pragma unroll
    for (int i = 0; i < W / 128; i++) {
        float4 v = xr[lane + i * 32];
        s  += v.x + v.y + v.z + v.w;
        sq += v.x * v.x + v.y * v.y + v.z * v.z + v.w * v.w;
    }
    #pragma unroll
    for (int o = 16; o; o >>= 1) {
        s  += __shfl_xor_sync(0xffffffffu, s,  o);
        sq += __shfl_xor_sync(0xffffffffu, sq, o);
    }
    if (lane == 0) {
        float mu  = s * (1.0f / W);
        float var = sq * (1.0f / W) - mu * mu;
        st[warp] = make_float2(mu, rsqrtf(var + LN_EPS));
    }
}

// ---------------- mma / ldmatrix helpers ------------------------------------
__device__ __forceinline__ float f2tf32(float x) {
    unsigned r;
    asm("cvt.rna.tf32.f32 %0, %1;" : "=r"(r) : "f"(x));
    return __uint_as_float(r);
}
__device__ __forceinline__ void mma_tf32(float* c, const unsigned* a, const unsigned* b) {
    asm volatile(
        "mma.sync.aligned.m16n8k8.row.col.f32.tf32.tf32.f32 "
        "{%0,%1,%2,%3}, {%4,%5,%6,%7}, {%8,%9}, {%0,%1,%2,%3};"
        : "+f"(c[0]), "+f"(c[1]), "+f"(c[2]), "+f"(c[3])
        : "r"(a[0]), "r"(a[1]), "r"(a[2]), "r"(a[3]), "r"(b[0]), "r"(b[1]));
}
__device__ __forceinline__ void mma_bf16(float* c, const unsigned* a, const unsigned* b) {
    asm volatile(
        "mma.sync.aligned.m16n8k16.row.col.f32.bf16.bf16.f32 "
        "{%0,%1,%2,%3}, {%4,%5,%6,%7}, {%8,%9}, {%0,%1,%2,%3};"
        : "+f"(c[0]), "+f"(c[1]), "+f"(c[2]), "+f"(c[3])
        : "r"(a[0]), "r"(a[1]), "r"(a[2]), "r"(a[3]), "r"(b[0]), "r"(b[1]));
}
__device__ __forceinline__ unsigned pack_bf16(float a, float b) {
    unsigned r;
    asm("cvt.rn.bf16x2.f32 %0, %1, %2;" : "=r"(r) : "f"(b), "f"(a));
    return r;
}
__device__ __forceinline__ void ldsm4(unsigned& r0, unsigned& r1, unsigned& r2,
                                      unsigned& r3, unsigned addr) {
    asm volatile("ldmatrix.sync.aligned.m8n8.x4.shared.b16 {%0,%1,%2,%3}, [%4];"
                 : "=r"(r0), "=r"(r1), "=r"(r2), "=r"(r3) : "r"(addr));
}

template <int EPI>
__device__ __forceinline__ float epi_apply(float v) {
    if (EPI == 1) return 0.5f * v * (1.0f + erff(v * 0.70710678118654752f));
    return v;
}

// ============================================================================
// tf32 GEMM: C[M,N] = LNopt(A)[M,K] @ W[N,K]^T (+bias)(+gelu)
// BM=64*MT, BN=128, BK=32, 256 threads, warp grid 4x2, warp tile (16*MT)x64.
// ldmatrix fragment loads (tf32-as-b16 trick), register-staged prefetch.
// ============================================================================
template <int K, int EPI, int LN, int MT>
__global__ __launch_bounds__(256) void k_gemm_tf32(
    const float* __restrict__ A, const float* __restrict__ W,
    const float* __restrict__ bias, float* __restrict__ C, int M, int N,
    const float2* __restrict__ stats, const float* __restrict__ lng,
    const float* __restrict__ lnb) {
    const int BK = 32, PITCH = 36, BM = 64 * MT;
    __shared__ float As[BM * PITCH];
    __shared__ float Bs[128 * PITCH];
    int tid = threadIdx.x;
    int wid = tid >> 5, lane = tid & 31;
    int wm = wid >> 1, wn = wid & 1;
    int g = lane >> 2, tq = lane & 3;
    int lrow8 = lane & 7, grp = lane >> 3;
    int bm0 = blockIdx.x * BM, bn0 = blockIdx.y * 128;

    float acc[MT][8][4];
    #pragma unroll
    for (int mt = 0; mt < MT; mt++)
        #pragma unroll
        for (int nt = 0; nt < 8; nt++)
            #pragma unroll
            for (int i = 0; i < 4; i++) acc[mt][nt][i] = 0.0f;

    // ldmatrix base addresses
    unsigned aAddr[MT], bAddr[4];
    {
        unsigned ab = (unsigned)__cvta_generic_to_shared(As);
        unsigned bb = (unsigned)__cvta_generic_to_shared(Bs);
        #pragma unroll
        for (int mt = 0; mt < MT; mt++) {
            int rowA = wm * (16 * MT) + mt * 16 + lrow8 + ((grp & 1) << 3);
            aAddr[mt] = ab + (rowA * PITCH + ((grp >> 1) << 2)) * 4;
        }
        #pragma unroll
        for (int nt2 = 0; nt2 < 4; nt2++) {
            int rowB = wn * 64 + nt2 * 16 + lrow8 + ((grp >> 1) << 3);
            bAddr[nt2] = bb + (rowB * PITCH + ((grp & 1) << 2)) * 4;
        }
    }

    int lrow = tid >> 3, lc4 = tid & 7;
    float4 ar[2 * MT], br[4];

    // prologue load k0 = 0
    #pragma unroll
    for (int i = 0; i < 2 * MT; i++) {
        int row = lrow + i * 32;
        int gr = bm0 + row;
        float4 v = make_float4(0.f, 0.f, 0.f, 0.f);
        if (gr < M) {
            v = *(const float4*)(A + (size_t)gr * K + lc4 * 4);
            if (LN) {
                float2 st = stats[gr];
                float4 gg = ((const float4*)lng)[lc4];
                float4 bb = ((const float4*)lnb)[lc4];
                v.x = (v.x - st.x) * st.y * gg.x + bb.x;
                v.y = (v.y - st.x) * st.y * gg.y + bb.y;
                v.z = (v.z - st.x) * st.y * gg.z + bb.z;
                v.w = (v.w - st.x) * st.y * gg.w + bb.w;
            }
        }
        ar[i] = v;
    }
    #pragma unroll
    for (int i = 0; i < 4; i++)
        br[i] = *(const float4*)(W + (size_t)(bn0 + lrow + i * 32) * K + lc4 * 4);

    #pragma unroll 1
    for (int k0 = 0; k0 < K; k0 += BK) {
        #pragma unroll
        for (int i = 0; i < 2 * MT; i++) {
            float* da = &As[(lrow + i * 32) * PITCH + lc4 * 4];
            da[0] = f2tf32(ar[i].x); da[1] = f2tf32(ar[i].y);
            da[2] = f2tf32(ar[i].z); da[3] = f2tf32(ar[i].w);
        }
        #pragma unroll
        for (int i = 0; i < 4; i++) {
            float* db = &Bs[(lrow + i * 32) * PITCH + lc4 * 4];
            db[0] = f2tf32(br[i].x); db[1] = f2tf32(br[i].y);
            db[2] = f2tf32(br[i].z); db[3] = f2tf32(br[i].w);
        }
        __syncthreads();

        if (k0 + BK < K) {
            int kn = k0 + BK;
            #pragma unroll
            for (int i = 0; i < 2 * MT; i++) {
                int row = lrow + i * 32;
                int gr = bm0 + row;
                float4 v = make_float4(0.f, 0.f, 0.f, 0.f);
                if (gr < M) {
                    v = *(const float4*)(A + (size_t)gr * K + kn + lc4 * 4);
                    if (LN) {
                        float2 st = stats[gr];
                        float4 gg = ((const float4*)lng)[kn / 4 + lc4];
                        float4 bb = ((const float4*)lnb)[kn / 4 + lc4];
                        v.x = (v.x - st.x) * st.y * gg.x + bb.x;
                        v.y = (v.y - st.x) * st.y * gg.y + bb.y;
                        v.z = (v.z - st.x) * st.y * gg.z + bb.z;
                        v.w = (v.w - st.x) * st.y * gg.w + bb.w;
                    }
                }
                ar[i] = v;
            }
            #pragma unroll
            for (int i = 0; i < 4; i++)
                br[i] = *(const float4*)(W + (size_t)(bn0 + lrow + i * 32) * K + kn + lc4 * 4);
        }

        #pragma unroll
        for (int ks = 0; ks < 4; ks++) {
            unsigned af[MT][4], bfv[8][2];
            #pragma unroll
            for (int mt = 0; mt < MT; mt++)
                ldsm4(af[mt][0], af[mt][1], af[mt][2], af[mt][3], aAddr[mt] + ks * 32);
            #pragma unroll
            for (int nt2 = 0; nt2 < 4; nt2++) {
                unsigned r0, r1, r2, r3;
                ldsm4(r0, r1, r2, r3, bAddr[nt2] + ks * 32);
                bfv[nt2 * 2][0] = r0; bfv[nt2 * 2][1] = r1;
                bfv[nt2 * 2 + 1][0] = r2; bfv[nt2 * 2 + 1][1] = r3;
            }
            #pragma unroll
            for (int mt = 0; mt < MT; mt++)
                #pragma unroll
                for (int nt = 0; nt < 8; nt++)
                    mma_tf32(acc[mt][nt], af[mt], bfv[nt]);
        }
        __syncthreads();
    }

    #pragma unroll
    for (int mt = 0; mt < MT; mt++) {
        int r0 = bm0 + wm * (16 * MT) + mt * 16 + g;
        #pragma unroll
        for (int nt = 0; nt < 8; nt++) {
            int c0 = bn0 + wn * 64 + nt * 8 + 2 * tq;
            float bv0 = bias ? bias[c0]     : 0.0f;
            float bv1 = bias ? bias[c0 + 1] : 0.0f;
            if (r0 < M) {
                C[(size_t)r0 * N + c0]     = epi_apply<EPI>(acc[mt][nt][0] + bv0);
                C[(size_t)r0 * N + c0 + 1] = epi_apply<EPI>(acc[mt][nt][1] + bv1);
            }
            if (r0 + 8 < M) {
                C[(size_t)(r0 + 8) * N + c0]     = epi_apply<EPI>(acc[mt][nt][2] + bv0);
                C[(size_t)(r0 + 8) * N + c0 + 1] = epi_apply<EPI>(acc[mt][nt][3] + bv1);
            }
        }
    }
}

// ============================================================================
// bf16 GEMM (GEMM2): xw_bf16[M,N] = LN2(A)[M,K] @ W[N,K]^T   K=N=256, BM=128
// ============================================================================
template <int K>
__global__ __launch_bounds__(256) void k_gemm_bf16(
    const float* __restrict__ A, const float* __restrict__ W,
    __nv_bfloat16* __restrict__ C, int M, int N,
    const float2* __restrict__ stats, const float* __restrict__ lng,
    const float* __restrict__ lnb) {
    const int BK = 32, PW = 20;   // u32 words per row (16 data + 4 pad), 80 B
    __shared__ unsigned As[128 * PW];
    __shared__ unsigned Bs[128 * PW];
    int tid = threadIdx.x;
    int wid = tid >> 5, lane = tid & 31;
    int wm = wid >> 1, wn = wid & 1;
    int g = lane >> 2, tq = lane & 3;
    int lrow8 = lane & 7, grp = lane >> 3;
    int bm0 = blockIdx.x * 128, bn0 = blockIdx.y * 128;

    float acc[2][8][4];
    #pragma unroll
    for (int mt = 0; mt < 2; mt++)
        #pragma unroll
        for (int nt = 0; nt < 8; nt++)
            #pragma unroll
            for (int i = 0; i < 4; i++) acc[mt][nt][i] = 0.0f;

    unsigned aAddr[2], bAddr[4];
    {
        unsigned ab = (unsigned)__cvta_generic_to_shared(As);
        unsigned bb = (unsigned)__cvta_generic_to_shared(Bs);
        #pragma unroll
        for (int mt = 0; mt < 2; mt++) {
            int rowA = wm * 32 + mt * 16 + lrow8 + ((grp & 1) << 3);
            aAddr[mt] = ab + rowA * (PW * 4) + ((grp >> 1) << 4);
        }
        #pragma unroll
        for (int nt2 = 0; nt2 < 4; nt2++) {
            int rowB = wn * 64 + nt2 * 16 + lrow8 + ((grp >> 1) << 3);
            bAddr[nt2] = bb + rowB * (PW * 4) + ((grp & 1) << 4);
        }
    }

    int lrow = tid >> 3, lc4 = tid & 7;
    float4 ar[4], br[4];

    #pragma unroll
    for (int i = 0; i < 4; i++) {
        int row = lrow + i * 32;
        int gr = bm0 + row;
        float4 v = make_float4(0.f, 0.f, 0.f, 0.f);
        if (gr < M) {
            v = *(const float4*)(A + (size_t)gr * K + lc4 * 4);
            float2 st = stats[gr];
            float4 gg = ((const float4*)lng)[lc4];
            float4 bb = ((const float4*)lnb)[lc4];
            v.x = (v.x - st.x) * st.y * gg.x + bb.x;
            v.y = (v.y - st.x) * st.y * gg.y + bb.y;
            v.z = (v.z - st.x) * st.y * gg.z + bb.z;
            v.w = (v.w - st.x) * st.y * gg.w + bb.w;
        }
        ar[i] = v;
        br[i] = *(const float4*)(W + (size_t)(bn0 + row) * K + lc4 * 4);
    }

    #pragma unroll 1
    for (int k0 = 0; k0 < K; k0 += BK) {
        #pragma unroll
        for (int i = 0; i < 4; i++) {
            int row = lrow + i * 32;
            As[row * PW + lc4 * 2]     = pack_bf16(ar[i].x, ar[i].y);
            As[row * PW + lc4 * 2 + 1] = pack_bf16(ar[i].z, ar[i].w);
            Bs[row * PW + lc4 * 2]     = pack_bf16(br[i].x, br[i].y);
            Bs[row * PW + lc4 * 2 + 1] = pack_bf16(br[i].z, br[i].w);
        }
        __syncthreads();

        if (k0 + BK < K) {
            int kn = k0 + BK;
            #pragma unroll
            for (int i = 0; i < 4; i++) {
                int row = lrow + i * 32;
                int gr = bm0 + row;
                float4 v = make_float4(0.f, 0.f, 0.f, 0.f);
                if (gr < M) {
                    v = *(const float4*)(A + (size_t)gr * K + kn + lc4 * 4);
                    float2 st = stats[gr];
                    float4 gg = ((const float4*)lng)[kn / 4 + lc4];
                    float4 bb = ((const float4*)lnb)[kn / 4 + lc4];
                    v.x = (v.x - st.x) * st.y * gg.x + bb.x;
                    v.y = (v.y - st.x) * st.y * gg.y + bb.y;
                    v.z = (v.z - st.x) * st.y * gg.z + bb.z;
                    v.w = (v.w - st.x) * st.y * gg.w + bb.w;
                }
                ar[i] = v;
                br[i] = *(const float4*)(W + (size_t)(bn0 + row) * K + kn + lc4 * 4);
            }
        }

        #pragma unroll
        for (int ks = 0; ks < 2; ks++) {     // k16 per mma
            unsigned af[2][4], bfv[8][2];
            #pragma unroll
            for (int mt = 0; mt < 2; mt++)
                ldsm4(af[mt][0], af[mt][1], af[mt][2], af[mt][3], aAddr[mt] + ks * 32);
            #pragma unroll
            for (int nt2 = 0; nt2 < 4; nt2++) {
                unsigned r0, r1, r2, r3;
                ldsm4(r0, r1, r2, r3, bAddr[nt2] + ks * 32);
                bfv[nt2 * 2][0] = r0; bfv[nt2 * 2][1] = r1;
                bfv[nt2 * 2 + 1][0] = r2; bfv[nt2 * 2 + 1][1] = r3;
            }
            #pragma unroll
            for (int mt = 0; mt < 2; mt++)
                #pragma unroll
                for (int nt = 0; nt < 8; nt++)
                    mma_bf16(acc[mt][nt], af[mt], bfv[nt]);
        }
        __syncthreads();
    }

    #pragma unroll
    for (int mt = 0; mt < 2; mt++) {
        int r0 = bm0 + wm * 32 + mt * 16 + g;
        #pragma unroll
        for (int nt = 0; nt < 8; nt++) {
            int c0 = bn0 + wn * 64 + nt * 8 + 2 * tq;
            if (r0 < M)
                *(unsigned*)(C + (size_t)r0 * N + c0) = pack_bf16(acc[mt][nt][0], acc[mt][nt][1]);
            if (r0 + 8 < M)
                *(unsigned*)(C + (size_t)(r0 + 8) * N + c0) = pack_bf16(acc[mt][nt][2], acc[mt][nt][3]);
        }
    }
}

// ---------------- fused GCN gather + gate (bf16 xw) -------------------------
__global__ __launch_bounds__(256) void k_gather(const float* __restrict__ bg) {
    int warp = (blockIdx.x * blockDim.x + threadIdx.x) >> 5;
    if (warp >= N_NODES) return;
    int lane = threadIdx.x & 31;

    float dvd = g_dinv[warp];
    float selfc = 2.0f * dvd * dvd;

    float a[8];
    {
        float4 b0 = ((const float4*)bg)[2 * lane];
        float4 b1 = ((const float4*)bg)[2 * lane + 1];
        uint4 q = ((const uint4*)(g_xw + (size_t)warp * FFN))[lane];
        const __nv_bfloat162* p = (const __nv_bfloat162*)&q;
        float2 v0 = __bfloat1622float2(p[0]);
        float2 v1 = __bfloat1622float2(p[1]);
        float2 v2 = __bfloat1622float2(p[2]);
        float2 v3 = __bfloat1622float2(p[3]);
        a[0] = b0.x + selfc * v0.x; a[1] = b0.y + selfc * v0.y;
        a[2] = b0.z + selfc * v1.x; a[3] = b0.w + selfc * v1.y;
        a[4] = b1.x + selfc * v2.x; a[5] = b1.y + selfc * v2.y;
        a[6] = b1.z + selfc * v3.x; a[7] = b1.w + selfc * v3.y;
    }

    int e   = g_rowptr[warp];
    int end = g_rowptr[warp + 1];

    for (; e + 4 <= end; e += 4) {
        int s0 = g_csr[e], s1 = g_csr[e + 1], s2 = g_csr[e + 2], s3 = g_csr[e + 3];
        float c0 = g_dinv[s0] * dvd, c1 = g_dinv[s1] * dvd;
        float c2 = g_dinv[s2] * dvd, c3 = g_dinv[s3] * dvd;
        uint4 q0 = ((const uint4*)(g_xw + (size_t)s0 * FFN))[lane];
        uint4 q1 = ((const uint4*)(g_xw + (size_t)s1 * FFN))[lane];
        uint4 q2 = ((const uint4*)(g_xw + (size_t)s2 * FFN))[lane];
        uint4 q3 = ((const uint4*)(g_xw + (size_t)s3 * FFN))[lane];
        #pragma unroll
        for (int j = 0; j < 4; j++) {
            float2 w0 = __bfloat1622float2(((const __nv_bfloat162*)&q0)[j]);
            float2 w1 = __bfloat1622float2(((const __nv_bfloat162*)&q1)[j]);
            float2 w2 = __bfloat1622float2(((const __nv_bfloat162*)&q2)[j]);
            float2 w3 = __bfloat1622float2(((const __nv_bfloat162*)&q3)[j]);
            a[2*j]   += c0 * w0.x + c1 * w1.x + c2 * w2.x + c3 * w3.x;
            a[2*j+1] += c0 * w0.y + c1 * w1.y + c2 * w2.y + c3 * w3.y;
        }
    }
    for (; e < end; e++) {
        int s = g_csr[e];
        float c = g_dinv[s] * dvd;
        uint4 q = ((const uint4*)(g_xw + (size_t)s * FFN))[lane];
        #pragma unroll
        for (int j = 0; j < 4; j++) {
            float2 w = __bfloat1622float2(((const __nv_bfloat162*)&q)[j]);
            a[2*j]   += c * w.x;
            a[2*j+1] += c * w.y;
        }
    }

    const float4* hd = (const float4*)(g_h + (size_t)warp * FFN);
    float4* hgd = (float4*)(g_hg + (size_t)warp * FFN);
    #pragma unroll
    for (int j = 0; j < 2; j++) {
        float4 h = hd[2 * lane + j];
        float4 o;
        o.x = tanhf(a[4*j + 0]) * h.x;
        o.y = tanhf(a[4*j + 1]) * h.y;
        o.z = tanhf(a[4*j + 2]) * h.z;
        o.w = tanhf(a[4*j + 3]) * h.w;
        hgd[2 * lane + j] = o;
    }
}

// ---------------- host ------------------------------------------------------
extern "C" void kernel_launch(void* const* d_in, const int* in_sizes, int n_in,
                              void* d_out, int out_size) {
    const float* x     = (const float*)d_in[0];
    const void*  eidx  = d_in[1];
    const float* ln1_g = (const float*)d_in[2];
    const float* ln1_b = (const float*)d_in[3];
    const float* w_in  = (const float*)d_in[4];
    const float* b_in  = (const float*)d_in[5];
    const float* ln2_g = (const float*)d_in[6];
    const float* ln2_b = (const float*)d_in[7];
    const float* w_gcn = (const float*)d_in[8];
    const float* b_gcn = (const float*)d_in[9];
    const float* w_out = (const float*)d_in[10];
    const float* b_out = (const float*)d_in[11];
    float* out = (float*)d_out;

    int E = in_sizes[1] / 2;

    void *p_h, *p_xw, *p_hg, *p_st1, *p_st2;
    cudaGetSymbolAddress(&p_h,   g_h);
    cudaGetSymbolAddress(&p_xw,  g_xw);
    cudaGetSymbolAddress(&p_hg,  g_hg);
    cudaGetSymbolAddress(&p_st1, g_st1);
    cudaGetSymbolAddress(&p_st2, g_st2);

    const int TB = 256;
    int eblk = (E + TB - 1) / TB;
    int wblk = (N_NODES * 32 + TB - 1) / TB;

    // 1. init (zero hist + dtype detect) + CSR build + dinv
    k_init<<<NB_SCAN, 256>>>((const unsigned int*)eidx, 1024);
    k_hist<<<eblk, TB>>>(eidx, E);
    k_scan1<<<NB_SCAN, 256>>>();
    k_scan3<<<NB_SCAN, 256>>>(E);
    k_fill<<<eblk, TB>>>(eidx, E);

    // 2. LN1 stats; GEMM1 (fused LN1 + GELU): x -> h   [tf32, BM=128]
    k_lnstats<HIDDEN><<<wblk, TB>>>(x, (float2*)p_st1);
    {
        dim3 grid((N_NODES + 127) / 128, FFN / 128);
        k_gemm_tf32<HIDDEN, 1, 1, 2><<<grid, 256>>>(x, w_in, b_in, (float*)p_h,
                                                    N_NODES, FFN,
                                                    (const float2*)p_st1, ln1_g, ln1_b);
    }

    // 3. LN2 stats; GEMM2 (fused LN2): h -> xw (bf16)
    k_lnstats<FFN><<<wblk, TB>>>((const float*)p_h, (float2*)p_st2);
    {
        dim3 grid((N_NODES + 127) / 128, FFN / 128);
        k_gemm_bf16<FFN><<<grid, 256>>>((const float*)p_h, w_gcn,
                                        (__nv_bfloat16*)p_xw, N_NODES, FFN,
                                        (const float2*)p_st2, ln2_g, ln2_b);
    }

    // 4. fused gather + self-loop + bias + tanh-gate: -> hg
    k_gather<<<wblk, TB>>>(b_gcn);

    // 5. GEMM3: hg -> out   [tf32, BM=64 for tail efficiency]
    {
        dim3 grid((N_NODES + 63) / 64, HIDDEN / 128);
        k_gemm_tf32<FFN, 0, 0, 1><<<grid, 256>>>((const float*)p_hg, w_out, b_out,
                                                 out, N_NODES, HIDDEN,
                                                 nullptr, nullptr, nullptr);
    }
}

// round 11
// speedup vs baseline: 1.5209x; 1.0508x over previous
#include <cuda_runtime.h>
#include <cuda_bf16.h>
#include <math.h>
#include <stdint.h>

#define N_NODES 50000
#define HIDDEN  128
#define FFN     256
#define LN_EPS  1e-5f
#define MAX_E   524288
#define NB_SCAN 196   // ceil(50000/256)

// ---------------- scratch (static device globals; no allocation) ----------
__device__ __align__(16) float g_h [(size_t)N_NODES * FFN];          // gelu out (fp32)
__device__ __align__(16) __nv_bfloat16 g_xw[(size_t)N_NODES * FFN];  // gating gemm out
__device__ __align__(16) float g_hg[(size_t)N_NODES * FFN];          // tanh(agg)*h (fp32)
__device__ float  g_dinv[N_NODES];
__device__ int    g_cnt [N_NODES];
__device__ int    g_cur [N_NODES];
__device__ int    g_rowptr[N_NODES + 1];
__device__ int    g_bsum[256];
__device__ int    g_csr [MAX_E];
__device__ float2 g_st1[N_NODES];   // LN1 (mu, rstd) of x rows
__device__ float2 g_st2[N_NODES];   // (sum, sumsq) of h rows, filled by GEMM1
__device__ int    g_is64;

// ---------------- init: LN1 stats + zero hist/sums + dtype detect -----------
__global__ void k_init(const float* __restrict__ x, const unsigned int* __restrict__ w,
                       int nslots) {
    int gtid = blockIdx.x * blockDim.x + threadIdx.x;
    int warp = gtid >> 5;
    int lane = threadIdx.x & 31;

    if (warp < N_NODES) {
        float4 v = ((const float4*)(x + (size_t)warp * HIDDEN))[lane];
        float s  = v.x + v.y + v.z + v.w;
        float sq = v.x * v.x + v.y * v.y + v.z * v.z + v.w * v.w;
        #pragma unroll
        for (int o = 16; o; o >>= 1) {
            s  += __shfl_xor_sync(0xffffffffu, s,  o);
            sq += __shfl_xor_sync(0xffffffffu, sq, o);
        }
        if (lane == 0) {
            float mu  = s * (1.0f / HIDDEN);
            float var = sq * (1.0f / HIDDEN) - mu * mu;
            g_st1[warp] = make_float2(mu, rsqrtf(var + LN_EPS));
        }
    }
    if (gtid < N_NODES) {
        g_cnt[gtid] = 0;
        g_st2[gtid] = make_float2(0.f, 0.f);
    }
    if (blockIdx.x == 0) {
        __shared__ unsigned int red[256];
        unsigned int acc = 0;
        for (int j = threadIdx.x; j < nslots; j += blockDim.x) acc |= w[2 * j + 1];
        red[threadIdx.x] = acc;
        __syncthreads();
        for (int s = 128; s > 0; s >>= 1) {
            if (threadIdx.x < s) red[threadIdx.x] |= red[threadIdx.x + s];
            __syncthreads();
        }
        if (threadIdx.x == 0) g_is64 = (red[0] == 0u) ? 1 : 0;
    }
}

// ---------------- CSR build -------------------------------------------------
__global__ void k_hist(const void* __restrict__ eidx, int E) {
    int e = blockIdx.x * blockDim.x + threadIdx.x;
    if (e >= E) return;
    int d = g_is64 ? (int)((const long long*)eidx)[E + e]
                   : ((const int*)eidx)[E + e];
    atomicAdd(&g_cnt[d], 1);
}
__global__ void k_scan1() {
    __shared__ int sh[256];
    int t = threadIdx.x;
    int i = blockIdx.x * 256 + t;
    int v = (i < N_NODES) ? g_cnt[i] : 0;
    sh[t] = v;
    __syncthreads();
    #pragma unroll
    for (int off = 1; off < 256; off <<= 1) {
        int addend = (t >= off) ? sh[t - off] : 0;
        __syncthreads();
        sh[t] += addend;
        __syncthreads();
    }
    if (i < N_NODES) g_rowptr[i] = sh[t] - v;
    if (t == 255) g_bsum[blockIdx.x] = sh[255];
}
__global__ void k_scan3(int E) {
    __shared__ int sh[256];
    int t = threadIdx.x;
    int v = (t < NB_SCAN) ? g_bsum[t] : 0;
    sh[t] = v;
    __syncthreads();
    #pragma unroll
    for (int off = 1; off < 256; off <<= 1) {
        int addend = (t >= off) ? sh[t - off] : 0;
        __syncthreads();
        sh[t] += addend;
        __syncthreads();
    }
    int boff = (blockIdx.x > 0) ? sh[blockIdx.x - 1] : 0;
    int i = blockIdx.x * 256 + t;
    if (i < N_NODES) {
        g_rowptr[i] += boff;
        g_dinv[i] = rsqrtf((float)g_cnt[i] + 2.0f);
        g_cur[i] = 0;
    }
    if (i == 0) g_rowptr[N_NODES] = E;
}
__global__ void k_fill(const void* __restrict__ eidx, int E) {
    int e = blockIdx.x * blockDim.x + threadIdx.x;
    if (e >= E) return;
    int s, d;
    if (g_is64) {
        const long long* p = (const long long*)eidx;
        s = (int)p[e]; d = (int)p[E + e];
    } else {
        const int* p = (const int*)eidx;
        s = p[e]; d = p[E + e];
    }
    int pos = g_rowptr[d] + atomicAdd(&g_cur[d], 1);
    g_csr[pos] = s;
}

// ---------------- mma / ldmatrix helpers ------------------------------------
__device__ __forceinline__ float f2tf32(float x) {
    unsigned r;
    asm("cvt.rna.tf32.f32 %0, %1;" : "=r"(r) : "f"(x));
    return __uint_as_float(r);
}
__device__ __forceinline__ void mma_tf32(float* c, const unsigned* a, const unsigned* b) {
    asm volatile(
        "mma.sync.aligned.m16n8k8.row.col.f32.tf32.tf32.f32 "
        "{%0,%1,%2,%3}, {%4,%5,%6,%7}, {%8,%9}, {%0,%1,%2,%3};"
        : "+f"(c[0]), "+f"(c[1]), "+f"(c[2]), "+f"(c[3])
        : "r"(a[0]), "r"(a[1]), "r"(a[2]), "r"(a[3]), "r"(b[0]), "r"(b[1]));
}
__device__ __forceinline__ void mma_bf16(float* c, const unsigned* a, const unsigned* b) {
    asm volatile(
        "mma.sync.aligned.m16n8k16.row.col.f32.bf16.bf16.f32 "
        "{%0,%1,%2,%3}, {%4,%5,%6,%7}, {%8,%9}, {%0,%1,%2,%3};"
        : "+f"(c[0]), "+f"(c[1]), "+f"(c[2]), "+f"(c[3])
        : "r"(a[0]), "r"(a[1]), "r"(a[2]), "r"(a[3]), "r"(b[0]), "r"(b[1]));
}
__device__ __forceinline__ unsigned pack_bf16(float a, float b) {
    unsigned r;
    asm("cvt.rn.bf16x2.f32 %0, %1, %2;" : "=r"(r) : "f"(b), "f"(a));
    return r;
}
__device__ __forceinline__ void ldsm4(unsigned& r0, unsigned& r1, unsigned& r2,
                                      unsigned& r3, unsigned addr) {
    asm volatile("ldmatrix.sync.aligned.m8n8.x4.shared.b16 {%0,%1,%2,%3}, [%4];"
                 : "=r"(r0), "=r"(r1), "=r"(r2), "=r"(r3) : "r"(addr));
}
__device__ __forceinline__ float gelu_f(float v) {
    return 0.5f * v * (1.0f + erff(v * 0.70710678118654752f));
}

// ============================================================================
// GEMM1 (tf32): h_f32[M,256] = gelu(LN1(x)[M,128] @ w_in^T + b_in)
// Also accumulates per-row (sum, sumsq) of gelu output into g_st2 (LN2 stats).
// BM=128, BN=128, BK=32, 256 threads, warp grid 4x2, warp tile 32x64.
// ============================================================================
__global__ __launch_bounds__(256) void k_gemm1(
    const float* __restrict__ A, const float* __restrict__ W,
    const float* __restrict__ bias, float* __restrict__ C, int M,
    const float2* __restrict__ stats, const float* __restrict__ lng,
    const float* __restrict__ lnb) {
    const int K = 128, BK = 32, PITCH = 36;
    __shared__ float As[128 * PITCH];
    __shared__ float Bs[128 * PITCH];
    int tid = threadIdx.x;
    int wid = tid >> 5, lane = tid & 31;
    int wm = wid >> 1, wn = wid & 1;
    int g = lane >> 2, tq = lane & 3;
    int lrow8 = lane & 7, grp = lane >> 3;
    int bm0 = blockIdx.x * 128, bn0 = blockIdx.y * 128;

    float acc[2][8][4];
    #pragma unroll
    for (int mt = 0; mt < 2; mt++)
        #pragma unroll
        for (int nt = 0; nt < 8; nt++)
            #pragma unroll
            for (int i = 0; i < 4; i++) acc[mt][nt][i] = 0.0f;

    unsigned aAddr[2], bAddr[4];
    {
        unsigned ab = (unsigned)__cvta_generic_to_shared(As);
        unsigned bb = (unsigned)__cvta_generic_to_shared(Bs);
        #pragma unroll
        for (int mt = 0; mt < 2; mt++) {
            int rowA = wm * 32 + mt * 16 + lrow8 + ((grp & 1) << 3);
            aAddr[mt] = ab + (rowA * PITCH + ((grp >> 1) << 2)) * 4;
        }
        #pragma unroll
        for (int nt2 = 0; nt2 < 4; nt2++) {
            int rowB = wn * 64 + nt2 * 16 + lrow8 + ((grp >> 1) << 3);
            bAddr[nt2] = bb + (rowB * PITCH + ((grp & 1) << 2)) * 4;
        }
    }

    int lrow = tid >> 3, lc4 = tid & 7;
    float4 ar[4], br[4];

    #pragma unroll
    for (int i = 0; i < 4; i++) {
        int row = lrow + i * 32;
        int gr = bm0 + row;
        float4 v = make_float4(0.f, 0.f, 0.f, 0.f);
        if (gr < M) {
            v = *(const float4*)(A + (size_t)gr * K + lc4 * 4);
            float2 st = stats[gr];
            float4 gg = ((const float4*)lng)[lc4];
            float4 bb = ((const float4*)lnb)[lc4];
            v.x = (v.x - st.x) * st.y * gg.x + bb.x;
            v.y = (v.y - st.x) * st.y * gg.y + bb.y;
            v.z = (v.z - st.x) * st.y * gg.z + bb.z;
            v.w = (v.w - st.x) * st.y * gg.w + bb.w;
        }
        ar[i] = v;
        br[i] = *(const float4*)(W + (size_t)(bn0 + row) * K + lc4 * 4);
    }

    #pragma unroll 1
    for (int k0 = 0; k0 < K; k0 += BK) {
        #pragma unroll
        for (int i = 0; i < 4; i++) {
            int row = lrow + i * 32;
            float* da = &As[row * PITCH + lc4 * 4];
            da[0] = f2tf32(ar[i].x); da[1] = f2tf32(ar[i].y);
            da[2] = f2tf32(ar[i].z); da[3] = f2tf32(ar[i].w);
            float* db = &Bs[row * PITCH + lc4 * 4];
            db[0] = f2tf32(br[i].x); db[1] = f2tf32(br[i].y);
            db[2] = f2tf32(br[i].z); db[3] = f2tf32(br[i].w);
        }
        __syncthreads();

        if (k0 + BK < K) {
            int kn = k0 + BK;
            #pragma unroll
            for (int i = 0; i < 4; i++) {
                int row = lrow + i * 32;
                int gr = bm0 + row;
                float4 v = make_float4(0.f, 0.f, 0.f, 0.f);
                if (gr < M) {
                    v = *(const float4*)(A + (size_t)gr * K + kn + lc4 * 4);
                    float2 st = stats[gr];
                    float4 gg = ((const float4*)lng)[kn / 4 + lc4];
                    float4 bb = ((const float4*)lnb)[kn / 4 + lc4];
                    v.x = (v.x - st.x) * st.y * gg.x + bb.x;
                    v.y = (v.y - st.x) * st.y * gg.y + bb.y;
                    v.z = (v.z - st.x) * st.y * gg.z + bb.z;
                    v.w = (v.w - st.x) * st.y * gg.w + bb.w;
                }
                ar[i] = v;
                br[i] = *(const float4*)(W + (size_t)(bn0 + row) * K + kn + lc4 * 4);
            }
        }

        #pragma unroll
        for (int ks = 0; ks < 4; ks++) {
            unsigned af[2][4], bfv[8][2];
            #pragma unroll
            for (int mt = 0; mt < 2; mt++)
                ldsm4(af[mt][0], af[mt][1], af[mt][2], af[mt][3], aAddr[mt] + ks * 32);
            #pragma unroll
            for (int nt2 = 0; nt2 < 4; nt2++) {
                unsigned r0, r1, r2, r3;
                ldsm4(r0, r1, r2, r3, bAddr[nt2] + ks * 32);
                bfv[nt2 * 2][0] = r0; bfv[nt2 * 2][1] = r1;
                bfv[nt2 * 2 + 1][0] = r2; bfv[nt2 * 2 + 1][1] = r3;
            }
            #pragma unroll
            for (int mt = 0; mt < 2; mt++)
                #pragma unroll
                for (int nt = 0; nt < 8; nt++)
                    mma_tf32(acc[mt][nt], af[mt], bfv[nt]);
        }
        __syncthreads();
    }

    // epilogue: gelu -> fp32 store + per-row (sum, sumsq) accumulation
    #pragma unroll
    for (int mt = 0; mt < 2; mt++) {
        #pragma unroll
        for (int half = 0; half < 2; half++) {
            int r = bm0 + wm * 32 + mt * 16 + half * 8 + g;
            float s = 0.f, sq = 0.f;
            float v0s[8], v1s[8];
            #pragma unroll
            for (int nt = 0; nt < 8; nt++) {
                int c0 = bn0 + wn * 64 + nt * 8 + 2 * tq;
                float v0 = gelu_f(acc[mt][nt][half * 2 + 0] + bias[c0]);
                float v1 = gelu_f(acc[mt][nt][half * 2 + 1] + bias[c0 + 1]);
                v0s[nt] = v0; v1s[nt] = v1;
                s += v0 + v1;
                sq += v0 * v0 + v1 * v1;
            }
            if (r < M) {
                #pragma unroll
                for (int nt = 0; nt < 8; nt++) {
                    int c0 = bn0 + wn * 64 + nt * 8 + 2 * tq;
                    C[(size_t)r * FFN + c0]     = v0s[nt];
                    C[(size_t)r * FFN + c0 + 1] = v1s[nt];
                }
            }
            s  += __shfl_xor_sync(0xffffffffu, s, 1);
            s  += __shfl_xor_sync(0xffffffffu, s, 2);
            sq += __shfl_xor_sync(0xffffffffu, sq, 1);
            sq += __shfl_xor_sync(0xffffffffu, sq, 2);
            if (tq == 0 && r < M) {
                atomicAdd(&g_st2[r].x, s);
                atomicAdd(&g_st2[r].y, sq);
            }
        }
    }
}

// ============================================================================
// GEMM2 (bf16 mma): xw_bf16[M,256] = LN2(h)[M,256] @ w_gcn^T
// h fp32; LN2 (mu,rstd) derived from g_st2 (sum,sumsq) at A-load.
// BM=128, BN=128, BK=32, 256 threads.
// ============================================================================
__global__ __launch_bounds__(256) void k_gemm2(
    const float* __restrict__ A, const float* __restrict__ W,
    __nv_bfloat16* __restrict__ C, int M,
    const float2* __restrict__ sums, const float* __restrict__ lng,
    const float* __restrict__ lnb) {
    const int K = 256, BK = 32, PW = 20;
    __shared__ unsigned As[128 * PW];
    __shared__ unsigned Bs[128 * PW];
    int tid = threadIdx.x;
    int wid = tid >> 5, lane = tid & 31;
    int wm = wid >> 1, wn = wid & 1;
    int g = lane >> 2, tq = lane & 3;
    int lrow8 = lane & 7, grp = lane >> 3;
    int bm0 = blockIdx.x * 128, bn0 = blockIdx.y * 128;

    float acc[2][8][4];
    #pragma unroll
    for (int mt = 0; mt < 2; mt++)
        #pragma unroll
        for (int nt = 0; nt < 8; nt++)
            #pragma unroll
            for (int i = 0; i < 4; i++) acc[mt][nt][i] = 0.0f;

    unsigned aAddr[2], bAddr[4];
    {
        unsigned ab = (unsigned)__cvta_generic_to_shared(As);
        unsigned bb = (unsigned)__cvta_generic_to_shared(Bs);
        #pragma unroll
        for (int mt = 0; mt < 2; mt++) {
            int rowA = wm * 32 + mt * 16 + lrow8 + ((grp & 1) << 3);
            aAddr[mt] = ab + rowA * (PW * 4) + ((grp >> 1) << 4);
        }
        #pragma unroll
        for (int nt2 = 0; nt2 < 4; nt2++) {
            int rowB = wn * 64 + nt2 * 16 + lrow8 + ((grp >> 1) << 3);
            bAddr[nt2] = bb + rowB * (PW * 4) + ((grp & 1) << 4);
        }
    }

    int lrow = tid >> 3, lc4 = tid & 7;
    float4 ar[4], br[4];

    #pragma unroll
    for (int i = 0; i < 4; i++) {
        int row = lrow + i * 32;
        int gr = bm0 + row;
        float4 v = make_float4(0.f, 0.f, 0.f, 0.f);
        if (gr < M) {
            v = *(const float4*)(A + (size_t)gr * K + lc4 * 4);
            float2 sm = sums[gr];
            float mu = sm.x * (1.0f / 256.0f);
            float rstd = rsqrtf(sm.y * (1.0f / 256.0f) - mu * mu + LN_EPS);
            float4 gg = ((const float4*)lng)[lc4];
            float4 bb = ((const float4*)lnb)[lc4];
            v.x = (v.x - mu) * rstd * gg.x + bb.x;
            v.y = (v.y - mu) * rstd * gg.y + bb.y;
            v.z = (v.z - mu) * rstd * gg.z + bb.z;
            v.w = (v.w - mu) * rstd * gg.w + bb.w;
        }
        ar[i] = v;
        br[i] = *(const float4*)(W + (size_t)(bn0 + row) * K + lc4 * 4);
    }

    #pragma unroll 1
    for (int k0 = 0; k0 < K; k0 += BK) {
        #pragma unroll
        for (int i = 0; i < 4; i++) {
            int row = lrow + i * 32;
            As[row * PW + lc4 * 2]     = pack_bf16(ar[i].x, ar[i].y);
            As[row * PW + lc4 * 2 + 1] = pack_bf16(ar[i].z, ar[i].w);
            Bs[row * PW + lc4 * 2]     = pack_bf16(br[i].x, br[i].y);
            Bs[row * PW + lc4 * 2 + 1] = pack_bf16(br[i].z, br[i].w);
        }
        __syncthreads();

        if (k0 + BK < K) {
            int kn = k0 + BK;
            #pragma unroll
            for (int i = 0; i < 4; i++) {
                int row = lrow + i * 32;
                int gr = bm0 + row;
                float4 v = make_float4(0.f, 0.f, 0.f, 0.f);
                if (gr < M) {
                    v = *(const float4*)(A + (size_t)gr * K + kn + lc4 * 4);
                    float2 sm = sums[gr];
                    float mu = sm.x * (1.0f / 256.0f);
                    float rstd = rsqrtf(sm.y * (1.0f / 256.0f) - mu * mu + LN_EPS);
                    float4 gg = ((const float4*)lng)[kn / 4 + lc4];
                    float4 bb = ((const float4*)lnb)[kn / 4 + lc4];
                    v.x = (v.x - mu) * rstd * gg.x + bb.x;
                    v.y = (v.y - mu) * rstd * gg.y + bb.y;
                    v.z = (v.z - mu) * rstd * gg.z + bb.z;
                    v.w = (v.w - mu) * rstd * gg.w + bb.w;
                }
                ar[i] = v;
                br[i] = *(const float4*)(W + (size_t)(bn0 + row) * K + kn + lc4 * 4);
            }
        }

        #pragma unroll
        for (int ks = 0; ks < 2; ks++) {
            unsigned af[2][4], bfv[8][2];
            #pragma unroll
            for (int mt = 0; mt < 2; mt++)
                ldsm4(af[mt][0], af[mt][1], af[mt][2], af[mt][3], aAddr[mt] + ks * 32);
            #pragma unroll
            for (int nt2 = 0; nt2 < 4; nt2++) {
                unsigned r0, r1, r2, r3;
                ldsm4(r0, r1, r2, r3, bAddr[nt2] + ks * 32);
                bfv[nt2 * 2][0] = r0; bfv[nt2 * 2][1] = r1;
                bfv[nt2 * 2 + 1][0] = r2; bfv[nt2 * 2 + 1][1] = r3;
            }
            #pragma unroll
            for (int mt = 0; mt < 2; mt++)
                #pragma unroll
                for (int nt = 0; nt < 8; nt++)
                    mma_bf16(acc[mt][nt], af[mt], bfv[nt]);
        }
        __syncthreads();
    }

    #pragma unroll
    for (int mt = 0; mt < 2; mt++) {
        int r0 = bm0 + wm * 32 + mt * 16 + g;
        #pragma unroll
        for (int nt = 0; nt < 8; nt++) {
            int c0 = bn0 + wn * 64 + nt * 8 + 2 * tq;
            if (r0 < M)
                *(unsigned*)(C + (size_t)r0 * FFN + c0) = pack_bf16(acc[mt][nt][0], acc[mt][nt][1]);
            if (r0 + 8 < M)
                *(unsigned*)(C + (size_t)(r0 + 8) * FFN + c0) = pack_bf16(acc[mt][nt][2], acc[mt][nt][3]);
        }
    }
}

// ============================================================================
// GEMM3 (tf32): out[M,128] = hg[M,256] @ w_out^T + b_out
// BM=64, BN=128, BK=32, 256 threads, warp grid 4x2, warp tile 16x64.
// ============================================================================
__global__ __launch_bounds__(256) void k_gemm3(
    const float* __restrict__ A, const float* __restrict__ W,
    const float* __restrict__ bias, float* __restrict__ C, int M) {
    const int K = 256, N = 128, BK = 32, PITCH = 36, BM = 64;
    __shared__ float As[BM * PITCH];
    __shared__ float Bs[128 * PITCH];
    int tid = threadIdx.x;
    int wid = tid >> 5, lane = tid & 31;
    int wm = wid >> 1, wn = wid & 1;
    int g = lane >> 2, tq = lane & 3;
    int lrow8 = lane & 7, grp = lane >> 3;
    int bm0 = blockIdx.x * BM, bn0 = 0;

    float acc[8][4];
    #pragma unroll
    for (int nt = 0; nt < 8; nt++)
        #pragma unroll
        for (int i = 0; i < 4; i++) acc[nt][i] = 0.0f;

    unsigned aAddr, bAddr[4];
    {
        unsigned ab = (unsigned)__cvta_generic_to_shared(As);
        unsigned bb = (unsigned)__cvta_generic_to_shared(Bs);
        int rowA = wm * 16 + lrow8 + ((grp & 1) << 3);
        aAddr = ab + (rowA * PITCH + ((grp >> 1) << 2)) * 4;
        #pragma unroll
        for (int nt2 = 0; nt2 < 4; nt2++) {
            int rowB = wn * 64 + nt2 * 16 + lrow8 + ((grp >> 1) << 3);
            bAddr[nt2] = bb + (rowB * PITCH + ((grp & 1) << 2)) * 4;
        }
    }

    int lrow = tid >> 3, lc4 = tid & 7;
    float4 ar[2], br[4];

    #pragma unroll
    for (int i = 0; i < 2; i++) {
        int gr = bm0 + lrow + i * 32;
        ar[i] = (gr < M) ? *(const float4*)(A + (size_t)gr * K + lc4 * 4)
                         : make_float4(0.f, 0.f, 0.f, 0.f);
    }
    #pragma unroll
    for (int i = 0; i < 4; i++)
        br[i] = *(const float4*)(W + (size_t)(bn0 + lrow + i * 32) * K + lc4 * 4);

    #pragma unroll 1
    for (int k0 = 0; k0 < K; k0 += BK) {
        #pragma unroll
        for (int i = 0; i < 2; i++) {
            float* da = &As[(lrow + i * 32) * PITCH + lc4 * 4];
            da[0] = f2tf32(ar[i].x); da[1] = f2tf32(ar[i].y);
            da[2] = f2tf32(ar[i].z); da[3] = f2tf32(ar[i].w);
        }
        #pragma unroll
        for (int i = 0; i < 4; i++) {
            float* db = &Bs[(lrow + i * 32) * PITCH + lc4 * 4];
            db[0] = f2tf32(br[i].x); db[1] = f2tf32(br[i].y);
            db[2] = f2tf32(br[i].z); db[3] = f2tf32(br[i].w);
        }
        __syncthreads();

        if (k0 + BK < K) {
            int kn = k0 + BK;
            #pragma unroll
            for (int i = 0; i < 2; i++) {
                int gr = bm0 + lrow + i * 32;
                ar[i] = (gr < M) ? *(const float4*)(A + (size_t)gr * K + kn + lc4 * 4)
                                 : make_float4(0.f, 0.f, 0.f, 0.f);
            }
            #pragma unroll
            for (int i = 0; i < 4; i++)
                br[i] = *(const float4*)(W + (size_t)(bn0 + lrow + i * 32) * K + kn + lc4 * 4);
        }

        #pragma unroll
        for (int ks = 0; ks < 4; ks++) {
            unsigned af[4], bfv[8][2];
            ldsm4(af[0], af[1], af[2], af[3], aAddr + ks * 32);
            #pragma unroll
            for (int nt2 = 0; nt2 < 4; nt2++) {
                unsigned r0, r1, r2, r3;
                ldsm4(r0, r1, r2, r3, bAddr[nt2] + ks * 32);
                bfv[nt2 * 2][0] = r0; bfv[nt2 * 2][1] = r1;
                bfv[nt2 * 2 + 1][0] = r2; bfv[nt2 * 2 + 1][1] = r3;
            }
            #pragma unroll
            for (int nt = 0; nt < 8; nt++)
                mma_tf32(acc[nt], af, bfv[nt]);
        }
        __syncthreads();
    }

    int r0 = bm0 + wm * 16 + g;
    #pragma unroll
    for (int nt = 0; nt < 8; nt++) {
        int c0 = bn0 + wn * 64 + nt * 8 + 2 * tq;
        float bv0 = bias[c0], bv1 = bias[c0 + 1];
        if (r0 < M) {
            C[(size_t)r0 * N + c0]     = acc[nt][0] + bv0;
            C[(size_t)r0 * N + c0 + 1] = acc[nt][1] + bv1;
        }
        if (r0 + 8 < M) {
            C[(size_t)(r0 + 8) * N + c0]     = acc[nt][2] + bv0;
            C[(size_t)(r0 + 8) * N + c0 + 1] = acc[nt][3] + bv1;
        }
    }
}

// ---------------- fused GCN gather + gate (bf16 xw, fp32 h -> fp32 hg) ------
__global__ __launch_bounds__(256) void k_gather(const float* __restrict__ bg) {
    int warp = (blockIdx.x * blockDim.x + threadIdx.x) >> 5;
    if (warp >= N_NODES) return;
    int lane = threadIdx.x & 31;

    float dvd = g_dinv[warp];
    float selfc = 2.0f * dvd * dvd;

    float a[8];
    {
        float4 b0 = ((const float4*)bg)[2 * lane];
        float4 b1 = ((const float4*)bg)[2 * lane + 1];
        uint4 q = ((const uint4*)(g_xw + (size_t)warp * FFN))[lane];
        const __nv_bfloat162* p = (const __nv_bfloat162*)&q;
        float2 v0 = __bfloat1622float2(p[0]);
        float2 v1 = __bfloat1622float2(p[1]);
        float2 v2 = __bfloat1622float2(p[2]);
        float2 v3 = __bfloat1622float2(p[3]);
        a[0] = b0.x + selfc * v0.x; a[1] = b0.y + selfc * v0.y;
        a[2] = b0.z + selfc * v1.x; a[3] = b0.w + selfc * v1.y;
        a[4] = b1.x + selfc * v2.x; a[5] = b1.y + selfc * v2.y;
        a[6] = b1.z + selfc * v3.x; a[7] = b1.w + selfc * v3.y;
    }

    int e   = g_rowptr[warp];
    int end = g_rowptr[warp + 1];

    for (; e + 4 <= end; e += 4) {
        int s0 = g_csr[e], s1 = g_csr[e + 1], s2 = g_csr[e + 2], s3 = g_csr[e + 3];
        float c0 = g_dinv[s0] * dvd, c1 = g_dinv[s1] * dvd;
        float c2 = g_dinv[s2] * dvd, c3 = g_dinv[s3] * dvd;
        uint4 q0 = ((const uint4*)(g_xw + (size_t)s0 * FFN))[lane];
        uint4 q1 = ((const uint4*)(g_xw + (size_t)s1 * FFN))[lane];
        uint4 q2 = ((const uint4*)(g_xw + (size_t)s2 * FFN))[lane];
        uint4 q3 = ((const uint4*)(g_xw + (size_t)s3 * FFN))[lane];
        #pragma unroll
        for (int j = 0; j < 4; j++) {
            float2 w0 = __bfloat1622float2(((const __nv_bfloat162*)&q0)[j]);
            float2 w1 = __bfloat1622float2(((const __nv_bfloat162*)&q1)[j]);
            float2 w2 = __bfloat1622float2(((const __nv_bfloat162*)&q2)[j]);
            float2 w3 = __bfloat1622float2(((const __nv_bfloat162*)&q3)[j]);
            a[2*j]   += c0 * w0.x + c1 * w1.x + c2 * w2.x + c3 * w3.x;
            a[2*j+1] += c0 * w0.y + c1 * w1.y + c2 * w2.y + c3 * w3.y;
        }
    }
    for (; e < end; e++) {
        int s = g_csr[e];
        float c = g_dinv[s] * dvd;
        uint4 q = ((const uint4*)(g_xw + (size_t)s * FFN))[lane];
        #pragma unroll
        for (int j = 0; j < 4; j++) {
            float2 w = __bfloat1622float2(((const __nv_bfloat162*)&q)[j]);
            a[2*j]   += c * w.x;
            a[2*j+1] += c * w.y;
        }
    }

    // gate: hg = tanh(a) * h   (fp32)
    const float4* hd = (const float4*)(g_h + (size_t)warp * FFN);
    float4* hgd = (float4*)(g_hg + (size_t)warp * FFN);
    #pragma unroll
    for (int j = 0; j < 2; j++) {
        float4 h = hd[2 * lane + j];
        float4 o;
        o.x = tanhf(a[4*j + 0]) * h.x;
        o.y = tanhf(a[4*j + 1]) * h.y;
        o.z = tanhf(a[4*j + 2]) * h.z;
        o.w = tanhf(a[4*j + 3]) * h.w;
        hgd[2 * lane + j] = o;
    }
}

// ---------------- host ------------------------------------------------------
extern "C" void kernel_launch(void* const* d_in, const int* in_sizes, int n_in,
                              void* d_out, int out_size) {
    const float* x     = (const float*)d_in[0];
    const void*  eidx  = d_in[1];
    const float* ln1_g = (const float*)d_in[2];
    const float* ln1_b = (const float*)d_in[3];
    const float* w_in  = (const float*)d_in[4];
    const float* b_in  = (const float*)d_in[5];
    const float* ln2_g = (const float*)d_in[6];
    const float* ln2_b = (const float*)d_in[7];
    const float* w_gcn = (const float*)d_in[8];
    const float* b_gcn = (const float*)d_in[9];
    const float* w_out = (const float*)d_in[10];
    const float* b_out = (const float*)d_in[11];
    float* out = (float*)d_out;

    int E = in_sizes[1] / 2;

    void *p_h, *p_xw, *p_hg, *p_st1, *p_st2;
    cudaGetSymbolAddress(&p_h,   g_h);
    cudaGetSymbolAddress(&p_xw,  g_xw);
    cudaGetSymbolAddress(&p_hg,  g_hg);
    cudaGetSymbolAddress(&p_st1, g_st1);
    cudaGetSymbolAddress(&p_st2, g_st2);

    const int TB = 256;
    int eblk = (E + TB - 1) / TB;
    int wblk = (N_NODES * 32 + TB - 1) / TB;

    // 1. init (LN1 stats + zero hist/sums + dtype detect), CSR build + dinv
    k_init<<<wblk, TB>>>(x, (const unsigned int*)eidx, 1024);
    k_hist<<<eblk, TB>>>(eidx, E);
    k_scan1<<<NB_SCAN, 256>>>();
    k_scan3<<<NB_SCAN, 256>>>(E);
    k_fill<<<eblk, TB>>>(eidx, E);

    // 2. GEMM1 (tf32, fused LN1 + gelu + LN2-sum accumulation): x -> h (fp32)
    {
        dim3 grid((N_NODES + 127) / 128, FFN / 128);
        k_gemm1<<<grid, 256>>>(x, w_in, b_in, (float*)p_h, N_NODES,
                               (const float2*)p_st1, ln1_g, ln1_b);
    }

    // 3. GEMM2 (bf16 mma, fused LN2 from sums): h -> xw (bf16)
    {
        dim3 grid((N_NODES + 127) / 128, FFN / 128);
        k_gemm2<<<grid, 256>>>((const float*)p_h, w_gcn,
                               (__nv_bfloat16*)p_xw, N_NODES,
                               (const float2*)p_st2, ln2_g, ln2_b);
    }

    // 4. fused gather + self-loop + bias + tanh-gate: -> hg (fp32)
    k_gather<<<wblk, TB>>>(b_gcn);

    // 5. GEMM3 (tf32, BM=64): hg -> out
    {
        dim3 grid((N_NODES + 63) / 64, 1);
        k_gemm3<<<grid, 256>>>((const float*)p_hg, w_out, b_out, out, N_NODES);
    }
}

// round 15
// speedup vs baseline: 1.5853x; 1.0424x over previous
#include <cuda_runtime.h>
#include <cuda_bf16.h>
#include <math.h>
#include <stdint.h>

#define N_NODES 50000
#define HIDDEN  128
#define FFN     256
#define LN_EPS  1e-5f
#define MAX_E   524288
#define NB_SCAN 196   // ceil(50000/256)

// ---------------- scratch (static device globals; no allocation) ----------
__device__ __align__(16) float g_h [(size_t)N_NODES * FFN];          // gelu out (fp32)
__device__ __align__(16) __nv_bfloat16 g_xw[(size_t)N_NODES * FFN];  // gating gemm out
__device__ __align__(16) float g_hg[(size_t)N_NODES * FFN];          // tanh(agg)*h (fp32)
__device__ float  g_dinv[N_NODES];
__device__ int    g_cnt [N_NODES];
__device__ int    g_cur [N_NODES];
__device__ int    g_rowptr[N_NODES + 1];
__device__ int    g_bsum[256];
__device__ int    g_csr [MAX_E];
__device__ float2 g_st1[N_NODES];   // LN1 (mu, rstd) of x rows
__device__ float2 g_st2[N_NODES];   // (sum, sumsq) of h rows, filled by GEMM1
__device__ int    g_is64;

// ---------------- init: LN1 stats + zero hist/sums + dtype detect -----------
__global__ void k_init(const float* __restrict__ x, const unsigned int* __restrict__ w,
                       int nslots) {
    int gtid = blockIdx.x * blockDim.x + threadIdx.x;
    int warp = gtid >> 5;
    int lane = threadIdx.x & 31;

    if (gtid < N_NODES) {
        g_cnt[gtid] = 0;
        g_st2[gtid] = make_float2(0.f, 0.f);
    }
    if (warp < N_NODES) {
        float4 v = ((const float4*)(x + (size_t)warp * HIDDEN))[lane];
        float s  = v.x + v.y + v.z + v.w;
        float sq = v.x * v.x + v.y * v.y + v.z * v.z + v.w * v.w;
        #pragma unroll
        for (int o = 16; o; o >>= 1) {
            s  += __shfl_xor_sync(0xffffffffu, s,  o);
            sq += __shfl_xor_sync(0xffffffffu, sq, o);
        }
        if (lane == 0) {
            float mu  = s * (1.0f / HIDDEN);
            float var = sq * (1.0f / HIDDEN) - mu * mu;
            g_st1[warp] = make_float2(mu, rsqrtf(var + LN_EPS));
        }
    }
    if (blockIdx.x == 0) {
        __shared__ unsigned int red[256];
        unsigned int acc = 0;
        for (int j = threadIdx.x; j < nslots; j += blockDim.x) acc |= w[2 * j + 1];
        red[threadIdx.x] = acc;
        __syncthreads();
        for (int s = 128; s > 0; s >>= 1) {
            if (threadIdx.x < s) red[threadIdx.x] |= red[threadIdx.x + s];
            __syncthreads();
        }
        if (threadIdx.x == 0) g_is64 = (red[0] == 0u) ? 1 : 0;
    }
}

// ---------------- serial CSR tail -------------------------------------------
// scan block sums locally, add offset, init dinv + cursors
__global__ void k_scan3(int E) {
    __shared__ int sh[256];
    int t = threadIdx.x;
    int v = (t < NB_SCAN) ? g_bsum[t] : 0;
    sh[t] = v;
    __syncthreads();
    #pragma unroll
    for (int off = 1; off < 256; off <<= 1) {
        int addend = (t >= off) ? sh[t - off] : 0;
        __syncthreads();
        sh[t] += addend;
        __syncthreads();
    }
    int boff = (blockIdx.x > 0) ? sh[blockIdx.x - 1] : 0;
    int i = blockIdx.x * 256 + t;
    if (i < N_NODES) {
        g_rowptr[i] += boff;
        g_dinv[i] = rsqrtf((float)g_cnt[i] + 2.0f);
        g_cur[i] = 0;
    }
    if (i == 0) g_rowptr[N_NODES] = E;
}
__global__ void k_fill(const void* __restrict__ eidx, int E) {
    int e = blockIdx.x * blockDim.x + threadIdx.x;
    if (e >= E) return;
    int s, d;
    if (g_is64) {
        const long long* p = (const long long*)eidx;
        s = (int)p[e]; d = (int)p[E + e];
    } else {
        const int* p = (const int*)eidx;
        s = p[e]; d = p[E + e];
    }
    int pos = g_rowptr[d] + atomicAdd(&g_cur[d], 1);
    g_csr[pos] = s;
}

// ---------------- mma / ldmatrix helpers ------------------------------------
__device__ __forceinline__ float f2tf32(float x) {
    unsigned r;
    asm("cvt.rna.tf32.f32 %0, %1;" : "=r"(r) : "f"(x));
    return __uint_as_float(r);
}
__device__ __forceinline__ void mma_tf32(float* c, const unsigned* a, const unsigned* b) {
    asm volatile(
        "mma.sync.aligned.m16n8k8.row.col.f32.tf32.tf32.f32 "
        "{%0,%1,%2,%3}, {%4,%5,%6,%7}, {%8,%9}, {%0,%1,%2,%3};"
        : "+f"(c[0]), "+f"(c[1]), "+f"(c[2]), "+f"(c[3])
        : "r"(a[0]), "r"(a[1]), "r"(a[2]), "r"(a[3]), "r"(b[0]), "r"(b[1]));
}
__device__ __forceinline__ void mma_bf16(float* c, const unsigned* a, const unsigned* b) {
    asm volatile(
        "mma.sync.aligned.m16n8k16.row.col.f32.bf16.bf16.f32 "
        "{%0,%1,%2,%3}, {%4,%5,%6,%7}, {%8,%9}, {%0,%1,%2,%3};"
        : "+f"(c[0]), "+f"(c[1]), "+f"(c[2]), "+f"(c[3])
        : "r"(a[0]), "r"(a[1]), "r"(a[2]), "r"(a[3]), "r"(b[0]), "r"(b[1]));
}
__device__ __forceinline__ unsigned pack_bf16(float a, float b) {
    unsigned r;
    asm("cvt.rn.bf16x2.f32 %0, %1, %2;" : "=r"(r) : "f"(b), "f"(a));
    return r;
}
__device__ __forceinline__ void ldsm4(unsigned& r0, unsigned& r1, unsigned& r2,
                                      unsigned& r3, unsigned addr) {
    asm volatile("ldmatrix.sync.aligned.m8n8.x4.shared.b16 {%0,%1,%2,%3}, [%4];"
                 : "=r"(r0), "=r"(r1), "=r"(r2), "=r"(r3) : "r"(addr));
}
__device__ __forceinline__ float gelu_f(float v) {
    return 0.5f * v * (1.0f + erff(v * 0.70710678118654752f));
}

// ============================================================================
// GEMM1 (tf32): h_f32[M,256] = gelu(LN1(x)[M,128] @ w_in^T + b_in)
// Accumulates per-row (sum, sumsq) of gelu output into g_st2 (LN2 stats).
// Grid (391, 3): y in {0,1} = GEMM tiles; y == 2 = edge-histogram blocks
// (grid-stride over E) overlapped with the GEMM. Kernel boundary then
// guarantees the histogram is complete for scan1 inside GEMM2.
// ============================================================================
__global__ __launch_bounds__(256) void k_gemm1(
    const float* __restrict__ A, const float* __restrict__ W,
    const float* __restrict__ bias, float* __restrict__ C, int M,
    const float2* __restrict__ stats, const float* __restrict__ lng,
    const float* __restrict__ lnb, const void* __restrict__ eidx, int E) {
    const int K = 128, BK = 32, PITCH = 36;
    __shared__ float As[128 * PITCH];
    __shared__ float Bs[128 * PITCH];

    // ---- piggyback: histogram of destination nodes ----
    if (blockIdx.y == 2) {
        int stride = gridDim.x * blockDim.x;
        if (g_is64) {
            const long long* p = (const long long*)eidx;
            for (int e = blockIdx.x * blockDim.x + threadIdx.x; e < E; e += stride)
                atomicAdd(&g_cnt[(int)p[E + e]], 1);
        } else {
            const int* p = (const int*)eidx;
            for (int e = blockIdx.x * blockDim.x + threadIdx.x; e < E; e += stride)
                atomicAdd(&g_cnt[p[E + e]], 1);
        }
        return;
    }

    int tid = threadIdx.x;
    int wid = tid >> 5, lane = tid & 31;
    int wm = wid >> 1, wn = wid & 1;
    int g = lane >> 2, tq = lane & 3;
    int lrow8 = lane & 7, grp = lane >> 3;
    int bm0 = blockIdx.x * 128, bn0 = blockIdx.y * 128;

    float acc[2][8][4];
    #pragma unroll
    for (int mt = 0; mt < 2; mt++)
        #pragma unroll
        for (int nt = 0; nt < 8; nt++)
            #pragma unroll
            for (int i = 0; i < 4; i++) acc[mt][nt][i] = 0.0f;

    unsigned aAddr[2], bAddr[4];
    {
        unsigned ab = (unsigned)__cvta_generic_to_shared(As);
        unsigned bb = (unsigned)__cvta_generic_to_shared(Bs);
        #pragma unroll
        for (int mt = 0; mt < 2; mt++) {
            int rowA = wm * 32 + mt * 16 + lrow8 + ((grp & 1) << 3);
            aAddr[mt] = ab + (rowA * PITCH + ((grp >> 1) << 2)) * 4;
        }
        #pragma unroll
        for (int nt2 = 0; nt2 < 4; nt2++) {
            int rowB = wn * 64 + nt2 * 16 + lrow8 + ((grp >> 1) << 3);
            bAddr[nt2] = bb + (rowB * PITCH + ((grp & 1) << 2)) * 4;
        }
    }

    int lrow = tid >> 3, lc4 = tid & 7;
    float4 ar[4], br[4];

    #pragma unroll
    for (int i = 0; i < 4; i++) {
        int row = lrow + i * 32;
        int gr = bm0 + row;
        float4 v = make_float4(0.f, 0.f, 0.f, 0.f);
        if (gr < M) {
            v = *(const float4*)(A + (size_t)gr * K + lc4 * 4);
            float2 st = stats[gr];
            float4 gg = ((const float4*)lng)[lc4];
            float4 bb = ((const float4*)lnb)[lc4];
            v.x = (v.x - st.x) * st.y * gg.x + bb.x;
            v.y = (v.y - st.x) * st.y * gg.y + bb.y;
            v.z = (v.z - st.x) * st.y * gg.z + bb.z;
            v.w = (v.w - st.x) * st.y * gg.w + bb.w;
        }
        ar[i] = v;
        br[i] = *(const float4*)(W + (size_t)(bn0 + row) * K + lc4 * 4);
    }

    #pragma unroll 1
    for (int k0 = 0; k0 < K; k0 += BK) {
        #pragma unroll
        for (int i = 0; i < 4; i++) {
            int row = lrow + i * 32;
            float* da = &As[row * PITCH + lc4 * 4];
            da[0] = f2tf32(ar[i].x); da[1] = f2tf32(ar[i].y);
            da[2] = f2tf32(ar[i].z); da[3] = f2tf32(ar[i].w);
            float* db = &Bs[row * PITCH + lc4 * 4];
            db[0] = f2tf32(br[i].x); db[1] = f2tf32(br[i].y);
            db[2] = f2tf32(br[i].z); db[3] = f2tf32(br[i].w);
        }
        __syncthreads();

        if (k0 + BK < K) {
            int kn = k0 + BK;
            #pragma unroll
            for (int i = 0; i < 4; i++) {
                int row = lrow + i * 32;
                int gr = bm0 + row;
                float4 v = make_float4(0.f, 0.f, 0.f, 0.f);
                if (gr < M) {
                    v = *(const float4*)(A + (size_t)gr * K + kn + lc4 * 4);
                    float2 st = stats[gr];
                    float4 gg = ((const float4*)lng)[kn / 4 + lc4];
                    float4 bb = ((const float4*)lnb)[kn / 4 + lc4];
                    v.x = (v.x - st.x) * st.y * gg.x + bb.x;
                    v.y = (v.y - st.x) * st.y * gg.y + bb.y;
                    v.z = (v.z - st.x) * st.y * gg.z + bb.z;
                    v.w = (v.w - st.x) * st.y * gg.w + bb.w;
                }
                ar[i] = v;
                br[i] = *(const float4*)(W + (size_t)(bn0 + row) * K + kn + lc4 * 4);
            }
        }

        #pragma unroll
        for (int ks = 0; ks < 4; ks++) {
            unsigned af[2][4], bfv[8][2];
            #pragma unroll
            for (int mt = 0; mt < 2; mt++)
                ldsm4(af[mt][0], af[mt][1], af[mt][2], af[mt][3], aAddr[mt] + ks * 32);
            #pragma unroll
            for (int nt2 = 0; nt2 < 4; nt2++) {
                unsigned r0, r1, r2, r3;
                ldsm4(r0, r1, r2, r3, bAddr[nt2] + ks * 32);
                bfv[nt2 * 2][0] = r0; bfv[nt2 * 2][1] = r1;
                bfv[nt2 * 2 + 1][0] = r2; bfv[nt2 * 2 + 1][1] = r3;
            }
            #pragma unroll
            for (int mt = 0; mt < 2; mt++)
                #pragma unroll
                for (int nt = 0; nt < 8; nt++)
                    mma_tf32(acc[mt][nt], af[mt], bfv[nt]);
        }
        __syncthreads();
    }

    // epilogue: gelu -> fp32 store + per-row (sum, sumsq) accumulation
    #pragma unroll
    for (int mt = 0; mt < 2; mt++) {
        #pragma unroll
        for (int half = 0; half < 2; half++) {
            int r = bm0 + wm * 32 + mt * 16 + half * 8 + g;
            float s = 0.f, sq = 0.f;
            float v0s[8], v1s[8];
            #pragma unroll
            for (int nt = 0; nt < 8; nt++) {
                int c0 = bn0 + wn * 64 + nt * 8 + 2 * tq;
                float v0 = gelu_f(acc[mt][nt][half * 2 + 0] + bias[c0]);
                float v1 = gelu_f(acc[mt][nt][half * 2 + 1] + bias[c0 + 1]);
                v0s[nt] = v0; v1s[nt] = v1;
                s += v0 + v1;
                sq += v0 * v0 + v1 * v1;
            }
            if (r < M) {
                #pragma unroll
                for (int nt = 0; nt < 8; nt++) {
                    int c0 = bn0 + wn * 64 + nt * 8 + 2 * tq;
                    C[(size_t)r * FFN + c0]     = v0s[nt];
                    C[(size_t)r * FFN + c0 + 1] = v1s[nt];
                }
            }
            s  += __shfl_xor_sync(0xffffffffu, s, 1);
            s  += __shfl_xor_sync(0xffffffffu, s, 2);
            sq += __shfl_xor_sync(0xffffffffu, sq, 1);
            sq += __shfl_xor_sync(0xffffffffu, sq, 2);
            if (tq == 0 && r < M) {
                atomicAdd(&g_st2[r].x, s);
                atomicAdd(&g_st2[r].y, sq);
            }
        }
    }
}

// ============================================================================
// GEMM2 (bf16 mma): xw_bf16[M,256] = LN2(h)[M,256] @ w_gcn^T
// Grid (391, 3): y in {0,1} = GEMM tiles; y == 2, x < 196 = scan1 blocks
// (block-local exclusive scan of g_cnt into g_rowptr + block sums).
// ============================================================================
__global__ __launch_bounds__(256) void k_gemm2(
    const float* __restrict__ A, const float* __restrict__ W,
    __nv_bfloat16* __restrict__ C, int M,
    const float2* __restrict__ sums, const float* __restrict__ lng,
    const float* __restrict__ lnb) {
    const int K = 256, BK = 32, PW = 20;
    __shared__ unsigned As[128 * PW];
    __shared__ unsigned Bs[128 * PW];

    // ---- piggyback: scan1 (hist is complete: previous kernel boundary) ----
    if (blockIdx.y == 2) {
        if (blockIdx.x >= NB_SCAN) return;
        int* sh = (int*)As;
        int t = threadIdx.x;
        int i = blockIdx.x * 256 + t;
        int v = (i < N_NODES) ? g_cnt[i] : 0;
        sh[t] = v;
        __syncthreads();
        #pragma unroll
        for (int off = 1; off < 256; off <<= 1) {
            int addend = (t >= off) ? sh[t - off] : 0;
            __syncthreads();
            sh[t] += addend;
            __syncthreads();
        }
        if (i < N_NODES) g_rowptr[i] = sh[t] - v;
        if (t == 255) g_bsum[blockIdx.x] = sh[255];
        return;
    }

    int tid = threadIdx.x;
    int wid = tid >> 5, lane = tid & 31;
    int wm = wid >> 1, wn = wid & 1;
    int g = lane >> 2, tq = lane & 3;
    int lrow8 = lane & 7, grp = lane >> 3;
    int bm0 = blockIdx.x * 128, bn0 = blockIdx.y * 128;

    float acc[2][8][4];
    #pragma unroll
    for (int mt = 0; mt < 2; mt++)
        #pragma unroll
        for (int nt = 0; nt < 8; nt++)
            #pragma unroll
            for (int i = 0; i < 4; i++) acc[mt][nt][i] = 0.0f;

    unsigned aAddr[2], bAddr[4];
    {
        unsigned ab = (unsigned)__cvta_generic_to_shared(As);
        unsigned bb = (unsigned)__cvta_generic_to_shared(Bs);
        #pragma unroll
        for (int mt = 0; mt < 2; mt++) {
            int rowA = wm * 32 + mt * 16 + lrow8 + ((grp & 1) << 3);
            aAddr[mt] = ab + rowA * (PW * 4) + ((grp >> 1) << 4);
        }
        #pragma unroll
        for (int nt2 = 0; nt2 < 4; nt2++) {
            int rowB = wn * 64 + nt2 * 16 + lrow8 + ((grp >> 1) << 3);
            bAddr[nt2] = bb + rowB * (PW * 4) + ((grp & 1) << 4);
        }
    }

    int lrow = tid >> 3, lc4 = tid & 7;
    float4 ar[4], br[4];

    #pragma unroll
    for (int i = 0; i < 4; i++) {
        int row = lrow + i * 32;
        int gr = bm0 + row;
        float4 v = make_float4(0.f, 0.f, 0.f, 0.f);
        if (gr < M) {
            v = *(const float4*)(A + (size_t)gr * K + lc4 * 4);
            float2 sm = sums[gr];
            float mu = sm.x * (1.0f / 256.0f);
            float rstd = rsqrtf(sm.y * (1.0f / 256.0f) - mu * mu + LN_EPS);
            float4 gg = ((const float4*)lng)[lc4];
            float4 bb = ((const float4*)lnb)[lc4];
            v.x = (v.x - mu) * rstd * gg.x + bb.x;
            v.y = (v.y - mu) * rstd * gg.y + bb.y;
            v.z = (v.z - mu) * rstd * gg.z + bb.z;
            v.w = (v.w - mu) * rstd * gg.w + bb.w;
        }
        ar[i] = v;
        br[i] = *(const float4*)(W + (size_t)(bn0 + row) * K + lc4 * 4);
    }

    #pragma unroll 1
    for (int k0 = 0; k0 < K; k0 += BK) {
        #pragma unroll
        for (int i = 0; i < 4; i++) {
            int row = lrow + i * 32;
            As[row * PW + lc4 * 2]     = pack_bf16(ar[i].x, ar[i].y);
            As[row * PW + lc4 * 2 + 1] = pack_bf16(ar[i].z, ar[i].w);
            Bs[row * PW + lc4 * 2]     = pack_bf16(br[i].x, br[i].y);
            Bs[row * PW + lc4 * 2 + 1] = pack_bf16(br[i].z, br[i].w);
        }
        __syncthreads();

        if (k0 + BK < K) {
            int kn = k0 + BK;
            #pragma unroll
            for (int i = 0; i < 4; i++) {
                int row = lrow + i * 32;
                int gr = bm0 + row;
                float4 v = make_float4(0.f, 0.f, 0.f, 0.f);
                if (gr < M) {
                    v = *(const float4*)(A + (size_t)gr * K + kn + lc4 * 4);
                    float2 sm = sums[gr];
                    float mu = sm.x * (1.0f / 256.0f);
                    float rstd = rsqrtf(sm.y * (1.0f / 256.0f) - mu * mu + LN_EPS);
                    float4 gg = ((const float4*)lng)[kn / 4 + lc4];
                    float4 bb = ((const float4*)lnb)[kn / 4 + lc4];
                    v.x = (v.x - mu) * rstd * gg.x + bb.x;
                    v.y = (v.y - mu) * rstd * gg.y + bb.y;
                    v.z = (v.z - mu) * rstd * gg.z + bb.z;
                    v.w = (v.w - mu) * rstd * gg.w + bb.w;
                }
                ar[i] = v;
                br[i] = *(const float4*)(W + (size_t)(bn0 + row) * K + kn + lc4 * 4);
            }
        }

        #pragma unroll
        for (int ks = 0; ks < 2; ks++) {
            unsigned af[2][4], bfv[8][2];
            #pragma unroll
            for (int mt = 0; mt < 2; mt++)
                ldsm4(af[mt][0], af[mt][1], af[mt][2], af[mt][3], aAddr[mt] + ks * 32);
            #pragma unroll
            for (int nt2 = 0; nt2 < 4; nt2++) {
                unsigned r0, r1, r2, r3;
                ldsm4(r0, r1, r2, r3, bAddr[nt2] + ks * 32);
                bfv[nt2 * 2][0] = r0; bfv[nt2 * 2][1] = r1;
                bfv[nt2 * 2 + 1][0] = r2; bfv[nt2 * 2 + 1][1] = r3;
            }
            #pragma unroll
            for (int mt = 0; mt < 2; mt++)
                #pragma unroll
                for (int nt = 0; nt < 8; nt++)
                    mma_bf16(acc[mt][nt], af[mt], bfv[nt]);
        }
        __syncthreads();
    }

    #pragma unroll
    for (int mt = 0; mt < 2; mt++) {
        int r0 = bm0 + wm * 32 + mt * 16 + g;
        #pragma unroll
        for (int nt = 0; nt < 8; nt++) {
            int c0 = bn0 + wn * 64 + nt * 8 + 2 * tq;
            if (r0 < M)
                *(unsigned*)(C + (size_t)r0 * FFN + c0) = pack_bf16(acc[mt][nt][0], acc[mt][nt][1]);
            if (r0 + 8 < M)
                *(unsigned*)(C + (size_t)(r0 + 8) * FFN + c0) = pack_bf16(acc[mt][nt][2], acc[mt][nt][3]);
        }
    }
}

// ============================================================================
// GEMM3 (tf32): out[M,128] = hg[M,256] @ w_out^T + b_out
// BM=64, BN=128, BK=32, 256 threads, warp grid 4x2, warp tile 16x64.
// ============================================================================
__global__ __launch_bounds__(256) void k_gemm3(
    const float* __restrict__ A, const float* __restrict__ W,
    const float* __restrict__ bias, float* __restrict__ C, int M) {
    const int K = 256, N = 128, BK = 32, PITCH = 36, BM = 64;
    __shared__ float As[BM * PITCH];
    __shared__ float Bs[128 * PITCH];
    int tid = threadIdx.x;
    int wid = tid >> 5, lane = tid & 31;
    int wm = wid >> 1, wn = wid & 1;
    int g = lane >> 2, tq = lane & 3;
    int lrow8 = lane & 7, grp = lane >> 3;
    int bm0 = blockIdx.x * BM, bn0 = 0;

    float acc[8][4];
    #pragma unroll
    for (int nt = 0; nt < 8; nt++)
        #pragma unroll
        for (int i = 0; i < 4; i++) acc[nt][i] = 0.0f;

    unsigned aAddr, bAddr[4];
    {
        unsigned ab = (unsigned)__cvta_generic_to_shared(As);
        unsigned bb = (unsigned)__cvta_generic_to_shared(Bs);
        int rowA = wm * 16 + lrow8 + ((grp & 1) << 3);
        aAddr = ab + (rowA * PITCH + ((grp >> 1) << 2)) * 4;
        #pragma unroll
        for (int nt2 = 0; nt2 < 4; nt2++) {
            int rowB = wn * 64 + nt2 * 16 + lrow8 + ((grp >> 1) << 3);
            bAddr[nt2] = bb + (rowB * PITCH + ((grp & 1) << 2)) * 4;
        }
    }

    int lrow = tid >> 3, lc4 = tid & 7;
    float4 ar[2], br[4];

    #pragma unroll
    for (int i = 0; i < 2; i++) {
        int gr = bm0 + lrow + i * 32;
        ar[i] = (gr < M) ? *(const float4*)(A + (size_t)gr * K + lc4 * 4)
                         : make_float4(0.f, 0.f, 0.f, 0.f);
    }
    #pragma unroll
    for (int i = 0; i < 4; i++)
        br[i] = *(const float4*)(W + (size_t)(bn0 + lrow + i * 32) * K + lc4 * 4);

    #pragma unroll 1
    for (int k0 = 0; k0 < K; k0 += BK) {
        #pragma unroll
        for (int i = 0; i < 2; i++) {
            float* da = &As[(lrow + i * 32) * PITCH + lc4 * 4];
            da[0] = f2tf32(ar[i].x); da[1] = f2tf32(ar[i].y);
            da[2] = f2tf32(ar[i].z); da[3] = f2tf32(ar[i].w);
        }
        #pragma unroll
        for (int i = 0; i < 4; i++) {
            float* db = &Bs[(lrow + i * 32) * PITCH + lc4 * 4];
            db[0] = f2tf32(br[i].x); db[1] = f2tf32(br[i].y);
            db[2] = f2tf32(br[i].z); db[3] = f2tf32(br[i].w);
        }
        __syncthreads();

        if (k0 + BK < K) {
            int kn = k0 + BK;
            #pragma unroll
            for (int i = 0; i < 2; i++) {
                int gr = bm0 + lrow + i * 32;
                ar[i] = (gr < M) ? *(const float4*)(A + (size_t)gr * K + kn + lc4 * 4)
                                 : make_float4(0.f, 0.f, 0.f, 0.f);
            }
            #pragma unroll
            for (int i = 0; i < 4; i++)
                br[i] = *(const float4*)(W + (size_t)(bn0 + lrow + i * 32) * K + kn + lc4 * 4);
        }

        #pragma unroll
        for (int ks = 0; ks < 4; ks++) {
            unsigned af[4], bfv[8][2];
            ldsm4(af[0], af[1], af[2], af[3], aAddr + ks * 32);
            #pragma unroll
            for (int nt2 = 0; nt2 < 4; nt2++) {
                unsigned r0, r1, r2, r3;
                ldsm4(r0, r1, r2, r3, bAddr[nt2] + ks * 32);
                bfv[nt2 * 2][0] = r0; bfv[nt2 * 2][1] = r1;
                bfv[nt2 * 2 + 1][0] = r2; bfv[nt2 * 2 + 1][1] = r3;
            }
            #pragma unroll
            for (int nt = 0; nt < 8; nt++)
                mma_tf32(acc[nt], af, bfv[nt]);
        }
        __syncthreads();
    }

    int r0 = bm0 + wm * 16 + g;
    #pragma unroll
    for (int nt = 0; nt < 8; nt++) {
        int c0 = bn0 + wn * 64 + nt * 8 + 2 * tq;
        float bv0 = bias[c0], bv1 = bias[c0 + 1];
        if (r0 < M) {
            C[(size_t)r0 * N + c0]     = acc[nt][0] + bv0;
            C[(size_t)r0 * N + c0 + 1] = acc[nt][1] + bv1;
        }
        if (r0 + 8 < M) {
            C[(size_t)(r0 + 8) * N + c0]     = acc[nt][2] + bv0;
            C[(size_t)(r0 + 8) * N + c0 + 1] = acc[nt][3] + bv1;
        }
    }
}

// ---------------- fused GCN gather + gate (bf16 xw, fp32 h -> fp32 hg) ------
__global__ __launch_bounds__(256) void k_gather(const float* __restrict__ bg) {
    int warp = (blockIdx.x * blockDim.x + threadIdx.x) >> 5;
    if (warp >= N_NODES) return;
    int lane = threadIdx.x & 31;

    float dvd = g_dinv[warp];
    float selfc = 2.0f * dvd * dvd;

    float a[8];
    {
        float4 b0 = ((const float4*)bg)[2 * lane];
        float4 b1 = ((const float4*)bg)[2 * lane + 1];
        uint4 q = ((const uint4*)(g_xw + (size_t)warp * FFN))[lane];
        const __nv_bfloat162* p = (const __nv_bfloat162*)&q;
        float2 v0 = __bfloat1622float2(p[0]);
        float2 v1 = __bfloat1622float2(p[1]);
        float2 v2 = __bfloat1622float2(p[2]);
        float2 v3 = __bfloat1622float2(p[3]);
        a[0] = b0.x + selfc * v0.x; a[1] = b0.y + selfc * v0.y;
        a[2] = b0.z + selfc * v1.x; a[3] = b0.w + selfc * v1.y;
        a[4] = b1.x + selfc * v2.x; a[5] = b1.y + selfc * v2.y;
        a[6] = b1.z + selfc * v3.x; a[7] = b1.w + selfc * v3.y;
    }

    int e   = g_rowptr[warp];
    int end = g_rowptr[warp + 1];

    for (; e + 4 <= end; e += 4) {
        int s0 = g_csr[e], s1 = g_csr[e + 1], s2 = g_csr[e + 2], s3 = g_csr[e + 3];
        float c0 = g_dinv[s0] * dvd, c1 = g_dinv[s1] * dvd;
        float c2 = g_dinv[s2] * dvd, c3 = g_dinv[s3] * dvd;
        uint4 q0 = ((const uint4*)(g_xw + (size_t)s0 * FFN))[lane];
        uint4 q1 = ((const uint4*)(g_xw + (size_t)s1 * FFN))[lane];
        uint4 q2 = ((const uint4*)(g_xw + (size_t)s2 * FFN))[lane];
        uint4 q3 = ((const uint4*)(g_xw + (size_t)s3 * FFN))[lane];
        #pragma unroll
        for (int j = 0; j < 4; j++) {
            float2 w0 = __bfloat1622float2(((const __nv_bfloat162*)&q0)[j]);
            float2 w1 = __bfloat1622float2(((const __nv_bfloat162*)&q1)[j]);
            float2 w2 = __bfloat1622float2(((const __nv_bfloat162*)&q2)[j]);
            float2 w3 = __bfloat1622float2(((const __nv_bfloat162*)&q3)[j]);
            a[2*j]   += c0 * w0.x + c1 * w1.x + c2 * w2.x + c3 * w3.x;
            a[2*j+1] += c0 * w0.y + c1 * w1.y + c2 * w2.y + c3 * w3.y;
        }
    }
    for (; e < end; e++) {
        int s = g_csr[e];
        float c = g_dinv[s] * dvd;
        uint4 q = ((const uint4*)(g_xw + (size_t)s * FFN))[lane];
        #pragma unroll
        for (int j = 0; j < 4; j++) {
            float2 w = __bfloat1622float2(((const __nv_bfloat162*)&q)[j]);
            a[2*j]   += c * w.x;
            a[2*j+1] += c * w.y;
        }
    }

    // gate: hg = tanh(a) * h   (fp32)
    const float4* hd = (const float4*)(g_h + (size_t)warp * FFN);
    float4* hgd = (float4*)(g_hg + (size_t)warp * FFN);
    #pragma unroll
    for (int j = 0; j < 2; j++) {
        float4 h = hd[2 * lane + j];
        float4 o;
        o.x = tanhf(a[4*j + 0]) * h.x;
        o.y = tanhf(a[4*j + 1]) * h.y;
        o.z = tanhf(a[4*j + 2]) * h.z;
        o.w = tanhf(a[4*j + 3]) * h.w;
        hgd[2 * lane + j] = o;
    }
}

// ---------------- host ------------------------------------------------------
extern "C" void kernel_launch(void* const* d_in, const int* in_sizes, int n_in,
                              void* d_out, int out_size) {
    const float* x     = (const float*)d_in[0];
    const void*  eidx  = d_in[1];
    const float* ln1_g = (const float*)d_in[2];
    const float* ln1_b = (const float*)d_in[3];
    const float* w_in  = (const float*)d_in[4];
    const float* b_in  = (const float*)d_in[5];
    const float* ln2_g = (const float*)d_in[6];
    const float* ln2_b = (const float*)d_in[7];
    const float* w_gcn = (const float*)d_in[8];
    const float* b_gcn = (const float*)d_in[9];
    const float* w_out = (const float*)d_in[10];
    const float* b_out = (const float*)d_in[11];
    float* out = (float*)d_out;

    int E = in_sizes[1] / 2;

    void *p_h, *p_xw, *p_hg, *p_st1, *p_st2;
    cudaGetSymbolAddress(&p_h,   g_h);
    cudaGetSymbolAddress(&p_xw,  g_xw);
    cudaGetSymbolAddress(&p_hg,  g_hg);
    cudaGetSymbolAddress(&p_st1, g_st1);
    cudaGetSymbolAddress(&p_st2, g_st2);

    const int TB = 256;
    int eblk = (E + TB - 1) / TB;
    int wblk = (N_NODES * 32 + TB - 1) / TB;

    // 1. init: LN1 stats + zero hist/sums + dtype detect
    k_init<<<wblk, TB>>>(x, (const unsigned int*)eidx, 1024);

    // 2. GEMM1 (+ piggybacked edge histogram): x -> h (fp32), LN2 sums
    {
        dim3 grid((N_NODES + 127) / 128, FFN / 128 + 1);
        k_gemm1<<<grid, 256>>>(x, w_in, b_in, (float*)p_h, N_NODES,
                               (const float2*)p_st1, ln1_g, ln1_b, eidx, E);
    }

    // 3. GEMM2 (+ piggybacked scan1): h -> xw (bf16)
    {
        dim3 grid((N_NODES + 127) / 128, FFN / 128 + 1);
        k_gemm2<<<grid, 256>>>((const float*)p_h, w_gcn,
                               (__nv_bfloat16*)p_xw, N_NODES,
                               (const float2*)p_st2, ln2_g, ln2_b);
    }

    // 4. CSR tail: scan3 (rowptr offsets + dinv + cursors), fill
    k_scan3<<<NB_SCAN, 256>>>(E);
    k_fill <<<eblk, TB>>>(eidx, E);

    // 5. fused gather + self-loop + bias + tanh-gate: -> hg (fp32)
    k_gather<<<wblk, TB>>>(b_gcn);

    // 6. GEMM3 (tf32, BM=64): hg -> out
    {
        dim3 grid((N_NODES + 63) / 64, 1);
        k_gemm3<<<grid, 256>>>((const float*)p_hg, w_out, b_out, out, N_NODES);
    }
}